// round 15
// baseline (speedup 1.0000x reference)
#include <cuda_runtime.h>
#include <cuda_bf16.h>
#include <math.h>

#define BB 8
#define TT 96
#define EE 96
#define CC 256
#define HH 8
#define DD 32
#define HIDN 1024
#define NROWS (BB*TT*EE)   /* 73728 */
#define EPSI 1e-5f

// ---------------- scratch (static device globals; no allocations) ----------------
__device__ float g_X [NROWS*CC];            // running residual x (fp32)
__device__ float g_XA[NROWS*CC];            // xs fp32 (residual add in fuse1)
__device__ __nv_bfloat16 g_XAb[NROWS*CC];   // LN outputs, bf16 (GEMM A)
__device__ __nv_bfloat16 g_QKVb[NROWS*768]; // fused QKV output
__device__ __nv_bfloat16 g_Ob [NROWS*CC];
__device__ __nv_bfloat16 g_Pb [NROWS*CC];
__device__ __nv_bfloat16 g_Hb [NROWS*HIDN];
// transposed bf16 weights: [N][K] each
#define W_SQ 0
#define W_SK 65536
#define W_SV 131072
#define W_SP 196608
#define W_TQ 262144
#define W_TK 327680
#define W_TV 393216
#define W_TP 458752
#define W_M1 524288
#define W_M2 786432
#define W_TOT 1048576
__device__ __nv_bfloat16 g_WB[W_TOT];

__device__ __forceinline__ float warpSum(float v) {
    #pragma unroll
    for (int o = 16; o; o >>= 1) v += __shfl_xor_sync(0xffffffffu, v, o);
    return v;
}
__device__ __forceinline__ unsigned packbf(float lo, float hi) {
    unsigned r;
    asm("cvt.rn.bf16x2.f32 %0, %1, %2;" : "=r"(r) : "f"(hi), "f"(lo));
    return r;
}
__device__ __forceinline__ float2 upack2(unsigned u) {
    return __bfloat1622float2(*(__nv_bfloat162*)&u);
}
__device__ __forceinline__ void unpack4(uint2 v, float* f) {
    __nv_bfloat162* h = (__nv_bfloat162*)&v;
    float2 a = __bfloat1622float2(h[0]); float2 b = __bfloat1622float2(h[1]);
    f[0]=a.x; f[1]=a.y; f[2]=b.x; f[3]=b.y;
}

#define MMA16816(c0,c1,c2,c3,a0,a1,a2,a3,b0,b1) \
    asm volatile( \
        "mma.sync.aligned.m16n8k16.row.col.f32.bf16.bf16.f32 " \
        "{%0,%1,%2,%3},{%4,%5,%6,%7},{%8,%9},{%0,%1,%2,%3};" \
        : "+f"(c0), "+f"(c1), "+f"(c2), "+f"(c3) \
        : "r"(a0), "r"(a1), "r"(a2), "r"(a3), "r"(b0), "r"(b1))

#define LDSM4(r0,r1,r2,r3,addr) \
    asm volatile("ldmatrix.sync.aligned.m8n8.x4.shared.b16 {%0,%1,%2,%3}, [%4];" \
        : "=r"(r0), "=r"(r1), "=r"(r2), "=r"(r3) : "r"(addr))

__device__ __forceinline__ void cpa16(unsigned dst, const void* src) {
    asm volatile("cp.async.cg.shared.global [%0], [%1], 16;" :: "r"(dst), "l"(src));
}
#define CP_COMMIT() asm volatile("cp.async.commit_group;")
#define CP_WAIT1()  asm volatile("cp.async.wait_group 1;")
#define CP_WAIT0()  asm volatile("cp.async.wait_group 0;")

// ---------------- K0: weights -> transposed bf16 [N][K] ----------------
__global__ void k_wconv(const float* w0, const float* w1, const float* w2, const float* w3,
                        const float* w4, const float* w5, const float* w6, const float* w7,
                        const float* w8, const float* w9) {
    const float* srcs[10] = {w0,w1,w2,w3,w4,w5,w6,w7,w8,w9};
    const int offs[10] = {W_SQ,W_SK,W_SV,W_SP,W_TQ,W_TK,W_TV,W_TP,W_M1,W_M2};
    const int KsA[10]  = {256,256,256,256,256,256,256,256,256,1024};
    const int NsA[10]  = {256,256,256,256,256,256,256,256,1024,256};
    int gid = blockIdx.x * blockDim.x + threadIdx.x;   // 524288 threads
    int e0 = gid * 2;
    int seg;
    if (e0 < W_M1) seg = e0 >> 16;
    else if (e0 < W_M2) seg = 8;
    else seg = 9;
    int Ks = KsA[seg], Ns = NsA[seg];
    int rel2 = (e0 - offs[seg]) >> 1;
    int n = rel2 % Ns;
    int k0 = (rel2 / Ns) * 2;
    const float* s = srcs[seg];
    float lo = s[k0*Ns + n], hi = s[(k0+1)*Ns + n];
    *(unsigned*)(g_WB + offs[seg] + n*Ks + k0) = packbf(lo, hi);
}

// ---------------- K1: X = x ; XA = LN(x; n1) fp32 + bf16 ----------------
__global__ void k_ln1(const float* __restrict__ x,
                      const float* __restrict__ g, const float* __restrict__ b) {
    int warp = threadIdx.x >> 5, lane = threadIdx.x & 31;
    int row = blockIdx.x * 8 + warp;
    const float4* xr = (const float4*)(x + row*CC);
    float4 a0 = xr[lane], a1 = xr[lane+32];
    float4* Xr = (float4*)(g_X + row*CC);
    Xr[lane] = a0; Xr[lane+32] = a1;
    float f[8] = {a0.x,a0.y,a0.z,a0.w,a1.x,a1.y,a1.z,a1.w};
    float s = 0.f;
    #pragma unroll
    for (int j = 0; j < 8; j++) s += f[j];
    float m = warpSum(s) * (1.f/CC);
    float vs = 0.f;
    #pragma unroll
    for (int j = 0; j < 8; j++) { f[j] -= m; vs += f[j]*f[j]; }
    float r = rsqrtf(warpSum(vs) * (1.f/CC) + EPSI);
    float4 ga = ((const float4*)g)[lane], gb = ((const float4*)g)[lane+32];
    float4 ba = ((const float4*)b)[lane], bb = ((const float4*)b)[lane+32];
    float gf[8] = {ga.x,ga.y,ga.z,ga.w,gb.x,gb.y,gb.z,gb.w};
    float bf_[8] = {ba.x,ba.y,ba.z,ba.w,bb.x,bb.y,bb.z,bb.w};
    float o[8];
    #pragma unroll
    for (int j = 0; j < 8; j++) o[j] = f[j]*r*gf[j] + bf_[j];
    float4* Or = (float4*)(g_XA + row*CC);
    float4 o0 = {o[0],o[1],o[2],o[3]}, o1 = {o[4],o[5],o[6],o[7]};
    Or[lane] = o0; Or[lane+32] = o1;
    uint2* Ob2 = (uint2*)(g_XAb + row*CC);
    uint2 p0; p0.x = packbf(o[0],o[1]); p0.y = packbf(o[2],o[3]);
    uint2 p1; p1.x = packbf(o[4],o[5]); p1.y = packbf(o[6],o[7]);
    Ob2[lane] = p0; Ob2[lane+32] = p1;
}

// ---------------- bf16 GEMM 128x128x32; cp.async 3-stage + ldmatrix ------------
#define T_STRIDE_U32 20   /* 40 bf16 per row (32 data + 8 pad) */
#define STG 3
#define STAGE_U32 2560    /* 128 * 20 */
#define HG_SMEM (STG * 2 * STAGE_U32 * 4)   /* 61440 bytes */

template<int EPI, int OUTBF>
__global__ void __launch_bounds__(256)
hgemm_k(const __nv_bfloat16* __restrict__ A, const __nv_bfloat16* __restrict__ Bt,
        const float* __restrict__ bias, const float* __restrict__ Res,
        void* __restrict__ Cout, int M, int N, int K) {
    extern __shared__ unsigned smg[];   // [STG][2560] A stages, then [STG][2560] B stages

    int tid  = threadIdx.x;
    int bm   = blockIdx.y * 128, bn = blockIdx.x * 128;
    int lane = tid & 31, warp = tid >> 5;
    int wm   = (warp & 1) * 64, wn = (warp >> 1) * 32;
    int g    = lane >> 2, tig = lane & 3;

    int rowT = tid >> 2, colC = tid & 3;   // copy map: 64 rows x 4 chunks, 2 passes

    unsigned sbase;
    asm("{ .reg .u64 t; cvta.to.shared.u64 t, %1; cvt.u32.u64 %0, t; }"
        : "=r"(sbase) : "l"(smg));

    // per-lane ldmatrix offset (u32 units): matrix order m0(r0-7,k0-7) m1(r8-15,k0-7)
    // m2(r0-7,k8-15) m3(r8-15,k8-15)
    int lmOff = ((lane & 7) + ((lane >> 3) & 1) * 8) * T_STRIDE_U32 + (lane >> 4) * 4;

    float acc[4][4][4];
    #pragma unroll
    for (int i = 0; i < 4; i++)
        #pragma unroll
        for (int j = 0; j < 4; j++)
            #pragma unroll
            for (int k = 0; k < 4; k++) acc[i][j][k] = 0.f;

    int kTiles = K >> 5;

#define HG_ISSUE(st, kt) do { \
    int kOff = (kt) * 32; \
    const __nv_bfloat16* aS = &A [(bm + rowT) * K + kOff + colC * 8]; \
    const __nv_bfloat16* bS = &Bt[(bn + rowT) * K + kOff + colC * 8]; \
    unsigned aD = sbase + ((st) * STAGE_U32 + rowT * T_STRIDE_U32 + colC * 4) * 4; \
    unsigned bD = aD + STG * STAGE_U32 * 4; \
    cpa16(aD, aS);        cpa16(aD + 64 * T_STRIDE_U32 * 4, aS + 64 * K); \
    cpa16(bD, bS);        cpa16(bD + 64 * T_STRIDE_U32 * 4, bS + 64 * K); \
} while (0)

    int fetch = 0;
    for (; fetch < STG - 1 && fetch < kTiles; fetch++) { HG_ISSUE(fetch, fetch); CP_COMMIT(); }

    for (int kt = 0; kt < kTiles; ++kt) {
        if (fetch - kt > 1) CP_WAIT1(); else CP_WAIT0();
        __syncthreads();
        if (fetch < kTiles) { HG_ISSUE(fetch % STG, fetch); CP_COMMIT(); fetch++; }

        int st = kt % STG;
        unsigned aB = sbase + st * STAGE_U32 * 4;
        unsigned bB = aB + STG * STAGE_U32 * 4;
        #pragma unroll
        for (int kh = 0; kh < 2; ++kh) {
            unsigned af[4][4];
            #pragma unroll
            for (int mi = 0; mi < 4; ++mi) {
                unsigned ad = aB + ((wm + mi*16) * T_STRIDE_U32 + kh*8 + lmOff) * 4;
                LDSM4(af[mi][0], af[mi][1], af[mi][2], af[mi][3], ad);
            }
            unsigned bfr[4][2];
            #pragma unroll
            for (int nj = 0; nj < 2; ++nj) {
                unsigned bd = bB + ((wn + nj*16) * T_STRIDE_U32 + kh*8 + lmOff) * 4;
                unsigned r0, r1, r2, r3;
                LDSM4(r0, r1, r2, r3, bd);
                bfr[nj*2][0] = r0; bfr[nj*2+1][0] = r1;
                bfr[nj*2][1] = r2; bfr[nj*2+1][1] = r3;
            }
            #pragma unroll
            for (int mi = 0; mi < 4; ++mi)
                #pragma unroll
                for (int ni = 0; ni < 4; ++ni)
                    MMA16816(acc[mi][ni][0], acc[mi][ni][1], acc[mi][ni][2], acc[mi][ni][3],
                             af[mi][0], af[mi][1], af[mi][2], af[mi][3],
                             bfr[ni][0], bfr[ni][1]);
        }
    }

    #pragma unroll
    for (int mi = 0; mi < 4; ++mi) {
        int r0 = bm + wm + mi*16 + g;
        #pragma unroll
        for (int ni = 0; ni < 4; ++ni) {
            int c = bn + wn + ni*8 + tig*2;
            float v0 = acc[mi][ni][0], v1 = acc[mi][ni][1];
            float v2 = acc[mi][ni][2], v3 = acc[mi][ni][3];
            if (EPI >= 1) {
                float b0 = bias[c], b1 = bias[c+1];
                v0 += b0; v1 += b1; v2 += b0; v3 += b1;
            }
            if (EPI == 2) {
                v0 = 0.5f * v0 * (1.f + erff(v0 * 0.70710678118654752f));
                v1 = 0.5f * v1 * (1.f + erff(v1 * 0.70710678118654752f));
                v2 = 0.5f * v2 * (1.f + erff(v2 * 0.70710678118654752f));
                v3 = 0.5f * v3 * (1.f + erff(v3 * 0.70710678118654752f));
            }
            if (EPI == 3) {
                float2 ra = *(const float2*)&Res[r0 * N + c];
                float2 rb = *(const float2*)&Res[(r0 + 8) * N + c];
                v0 += ra.x; v1 += ra.y; v2 += rb.x; v3 += rb.y;
            }
            if (OUTBF) {
                unsigned* C32 = (unsigned*)Cout;
                C32[(r0 * N + c) >> 1]       = packbf(v0, v1);
                C32[((r0 + 8) * N + c) >> 1] = packbf(v2, v3);
            } else {
                float* Cf = (float*)Cout;
                float2 o0; o0.x = v0; o0.y = v1;
                float2 o1; o1.x = v2; o1.y = v3;
                *(float2*)&Cf[r0 * N + c]       = o0;
                *(float2*)&Cf[(r0 + 8) * N + c] = o1;
            }
        }
    }
}

// ---------------- attention via bf16 mma (reads fused QKV [NROWS][768]) --------
// compact smem 41.7 KB (5 CTAs/SM); warp-strip mapping with fragment reuse
#define O_SQ   0                  /* 96 x 20 u32 */
#define O_SK   1920
#define O_SVT  3840               /* 32 x 49 u32 (V transposed, stride 98 bf16) */
#define O_SS   5408               /* 96 x 52 u32 (96 bf16 data + pad) */
#define O_COL  10400              /* 32 fp32 colsums */
#define ATTN_U32 10432
#define ATTN_SMEM (ATTN_U32 * 4)  /* 41728 bytes */

template<bool TEMPORAL>
__global__ void __launch_bounds__(256)
attn_mma(const __nv_bfloat16* __restrict__ QKV, __nv_bfloat16* __restrict__ O,
         const float* __restrict__ adj) {
    extern __shared__ unsigned su[];
    unsigned* sQ  = su + O_SQ;
    unsigned* sK  = su + O_SK;
    unsigned* sVt = su + O_SVT;
    unsigned* sS  = su + O_SS;
    float* sCol   = (float*)(su + O_COL);

    int tid = threadIdx.x, lane = tid & 31, warp = tid >> 5;
    int g = lane >> 2, tig = lane & 3;
    int h = blockIdx.y;
    int row0, qstride, ostride;
    if (TEMPORAL) {
        int b = blockIdx.x / EE, e = blockIdx.x % EE;
        row0 = b*TT*EE + e;
        qstride = EE*768; ostride = EE*CC;
    } else {
        row0 = blockIdx.x * EE;
        qstride = 768; ostride = CC;
    }
    int qbase = row0*768 + h*DD;
    int obase = row0*CC  + h*DD;
    const __nv_bfloat16* Qp = QKV + qbase;
    const __nv_bfloat16* Kp = QKV + qbase + 256;
    const __nv_bfloat16* Vp = QKV + qbase + 512;

    // Q, K: 96 rows x 32 bf16 = 4 uint4 per row
    for (int i = tid; i < 96*4; i += 256) {
        int s = i >> 2, part = i & 3;
        uint4 q4 = *(const uint4*)&Qp[s*qstride + part*8];
        uint4 k4 = *(const uint4*)&Kp[s*qstride + part*8];
        unsigned* dq = &sQ[s*20 + part*4];
        dq[0]=q4.x; dq[1]=q4.y; dq[2]=q4.z; dq[3]=q4.w;
        unsigned* dk = &sK[s*20 + part*4];
        dk[0]=k4.x; dk[1]=k4.y; dk[2]=k4.z; dk[3]=k4.w;
    }
    // V transposed (u16 copy)
    const unsigned short* Vs = (const unsigned short*)Vp;
    for (int i = tid; i < 96*32; i += 256) {
        int s = i >> 5, d = i & 31;
        ((unsigned short*)sVt)[d*98 + s] = Vs[s*qstride + d];
    }
    __syncthreads();

    // spatial: fp32 column sums of V from smem (lane = d, stride-49 rows: conflict-free)
    if (!TEMPORAL && tid < 32) {
        const unsigned* vrow = &sVt[tid*49];
        float cs = 0.f;
        #pragma unroll 8
        for (int s2 = 0; s2 < 48; s2++) {
            float2 v = upack2(vrow[s2]);
            cs += v.x + v.y;
        }
        sCol[tid] = cs;
    }

    // S = Q K^T : warp w<6 owns full m16 x n96 strip; A fragments loaded ONCE
    if (warp < 6) {
        int m0 = warp * 16;
        int r0 = m0 + g, r1 = m0 + g + 8;
        unsigned aS[2][4];
        #pragma unroll
        for (int kh = 0; kh < 2; kh++) {
            const unsigned* p0 = &sQ[r0*20 + kh*8 + tig];
            const unsigned* p1 = &sQ[r1*20 + kh*8 + tig];
            aS[kh][0] = p0[0]; aS[kh][1] = p1[0];
            aS[kh][2] = p0[4]; aS[kh][3] = p1[4];
        }
        #pragma unroll
        for (int ni = 0; ni < 12; ni++) {
            int n0 = ni*8;
            float c0 = 0.f, c1 = 0.f, c2 = 0.f, c3 = 0.f;
            #pragma unroll
            for (int kh = 0; kh < 2; kh++) {
                unsigned b0 = sK[(n0+g)*20 + kh*8 + tig];
                unsigned b1 = sK[(n0+g)*20 + kh*8 + tig + 4];
                MMA16816(c0, c1, c2, c3,
                         aS[kh][0], aS[kh][1], aS[kh][2], aS[kh][3], b0, b1);
            }
            int cc = n0 + tig*2;
            if (TEMPORAL) {
                const float sc = 0.17677669529663687f;  // 1/sqrt(32)
                sS[r0*52 + ni*4 + tig] = packbf(c0*sc, c1*sc);
                sS[r1*52 + ni*4 + tig] = packbf(c2*sc, c3*sc);
            } else {
                float2 a0 = *(const float2*)&adj[r0*96 + cc];
                float2 a1 = *(const float2*)&adj[r1*96 + cc];
                sS[r0*52 + ni*4 + tig] = packbf(c0*a0.x*0.5f, c1*a0.y*0.5f);
                sS[r1*52 + ni*4 + tig] = packbf(c2*a1.x*0.5f, c3*a1.y*0.5f);
            }
        }
    }
    __syncthreads();

    if (TEMPORAL) {
        // in-place softmax on bf16 sS (fp32 math)
        for (int r = warp; r < 96; r += 8) {
            unsigned* row = &sS[r*52];
            float2 f0 = upack2(row[lane]);
            float f2 = -1e30f, f3 = -1e30f;
            if (lane < 16) {
                float2 t2 = upack2(row[32 + lane]);
                f2 = t2.x; f3 = t2.y;
            }
            float mx = fmaxf(fmaxf(f0.x, f0.y), fmaxf(f2, f3));
            #pragma unroll
            for (int o = 16; o; o >>= 1) mx = fmaxf(mx, __shfl_xor_sync(0xffffffffu, mx, o));
            float e0 = expf(f0.x - mx), e1 = expf(f0.y - mx);
            float e2 = (lane < 16) ? expf(f2 - mx) : 0.f;
            float e3 = (lane < 16) ? expf(f3 - mx) : 0.f;
            float s = warpSum(e0 + e1 + e2 + e3);
            float inv = 1.f / s;
            row[lane] = packbf(e0*inv, e1*inv);
            if (lane < 16) row[32 + lane] = packbf(e2*inv, e3*inv);
        }
        __syncthreads();
    }

    // O = S V : warp w<6 owns m16 x n32; ks-outer, A loaded once/ks
    unsigned* O32 = (unsigned*)O;
    if (warp < 6) {
        int m0 = warp * 16;
        int r0 = m0 + g, r1 = m0 + g + 8;
        float c[4][4];
        #pragma unroll
        for (int ni = 0; ni < 4; ni++)
            #pragma unroll
            for (int j = 0; j < 4; j++) c[ni][j] = 0.f;
        #pragma unroll
        for (int ks = 0; ks < 6; ks++) {
            unsigned a0 = sS[r0*52 + ks*8 + tig];
            unsigned a1 = sS[r1*52 + ks*8 + tig];
            unsigned a2 = sS[r0*52 + ks*8 + tig + 4];
            unsigned a3 = sS[r1*52 + ks*8 + tig + 4];
            #pragma unroll
            for (int ni = 0; ni < 4; ni++) {
                unsigned b0 = sVt[(ni*8+g)*49 + ks*8 + tig];
                unsigned b1 = sVt[(ni*8+g)*49 + ks*8 + tig + 4];
                MMA16816(c[ni][0], c[ni][1], c[ni][2], c[ni][3], a0, a1, a2, a3, b0, b1);
            }
        }
        #pragma unroll
        for (int ni = 0; ni < 4; ni++) {
            int cc = ni*8 + tig*2;
            float v0 = c[ni][0], v1 = c[ni][1], v2 = c[ni][2], v3 = c[ni][3];
            if (!TEMPORAL) {
                float ca = 0.5f * sCol[cc], cb = 0.5f * sCol[cc+1];
                v0 += ca; v1 += cb; v2 += ca; v3 += cb;
            }
            O32[(obase + r0*ostride + cc) >> 1] = packbf(v0, v1);
            O32[(obase + r1*ostride + cc) >> 1] = packbf(v2, v3);
        }
    }
}

// ---------------- K5: p=LN(Pb;s_n); x += xs + s_gamma*p; XAb = LN(x; n2) --------
__global__ void k_fuse1(const float* __restrict__ sng, const float* __restrict__ snb,
                        const float* __restrict__ sgam,
                        const float* __restrict__ n2g, const float* __restrict__ n2b) {
    int warp = threadIdx.x >> 5, lane = threadIdx.x & 31;
    int row = blockIdx.x * 8 + warp;
    int bidx = row*CC;
    uint2 pv0 = ((const uint2*)(g_Pb+bidx))[lane], pv1 = ((const uint2*)(g_Pb+bidx))[lane+32];
    float pf[8];
    unpack4(pv0, pf); unpack4(pv1, pf+4);
    float s = 0.f;
    #pragma unroll
    for (int j = 0; j < 8; j++) s += pf[j];
    float m1 = warpSum(s) * (1.f/CC);
    float vs = 0.f;
    #pragma unroll
    for (int j = 0; j < 8; j++) { pf[j] -= m1; vs += pf[j]*pf[j]; }
    float r1 = rsqrtf(warpSum(vs) * (1.f/CC) + EPSI);
    float4 ga = ((const float4*)sng)[lane], gb = ((const float4*)sng)[lane+32];
    float4 ba = ((const float4*)snb)[lane], bb = ((const float4*)snb)[lane+32];
    float gf[8] = {ga.x,ga.y,ga.z,ga.w,gb.x,gb.y,gb.z,gb.w};
    float bf_[8] = {ba.x,ba.y,ba.z,ba.w,bb.x,bb.y,bb.z,bb.w};
    float gamma = sgam[0];
    float4 x0 = ((const float4*)(g_X+bidx))[lane],  x1 = ((const float4*)(g_X+bidx))[lane+32];
    float4 s0 = ((const float4*)(g_XA+bidx))[lane], s1 = ((const float4*)(g_XA+bidx))[lane+32];
    float xf[8] = {x0.x,x0.y,x0.z,x0.w,x1.x,x1.y,x1.z,x1.w};
    float sf[8] = {s0.x,s0.y,s0.z,s0.w,s1.x,s1.y,s1.z,s1.w};
    float xn[8];
    #pragma unroll
    for (int j = 0; j < 8; j++)
        xn[j] = xf[j] + sf[j] + gamma * (pf[j]*r1*gf[j] + bf_[j]);
    float4 w0 = {xn[0],xn[1],xn[2],xn[3]}, w1 = {xn[4],xn[5],xn[6],xn[7]};
    ((float4*)(g_X+bidx))[lane] = w0; ((float4*)(g_X+bidx))[lane+32] = w1;
    float s2 = 0.f;
    #pragma unroll
    for (int j = 0; j < 8; j++) s2 += xn[j];
    float m2 = warpSum(s2) * (1.f/CC);
    float vs2 = 0.f;
    #pragma unroll
    for (int j = 0; j < 8; j++) { xn[j] -= m2; vs2 += xn[j]*xn[j]; }
    float r2 = rsqrtf(warpSum(vs2) * (1.f/CC) + EPSI);
    float4 g2a = ((const float4*)n2g)[lane], g2b = ((const float4*)n2g)[lane+32];
    float4 b2a = ((const float4*)n2b)[lane], b2b = ((const float4*)n2b)[lane+32];
    float g2f[8] = {g2a.x,g2a.y,g2a.z,g2a.w,g2b.x,g2b.y,g2b.z,g2b.w};
    float b2f[8] = {b2a.x,b2a.y,b2a.z,b2a.w,b2b.x,b2b.y,b2b.z,b2b.w};
    float o[8];
    #pragma unroll
    for (int j = 0; j < 8; j++) o[j] = xn[j]*r2*g2f[j] + b2f[j];
    uint2* Ob2 = (uint2*)(g_XAb + bidx);
    uint2 q0; q0.x = packbf(o[0],o[1]); q0.y = packbf(o[2],o[3]);
    uint2 q1; q1.x = packbf(o[4],o[5]); q1.y = packbf(o[6],o[7]);
    Ob2[lane] = q0; Ob2[lane+32] = q1;
}

// ---------------- K9: x += t_gamma*Pb; XAb = LN(x; n3) ----------------
__global__ void k_fuse2(const float* __restrict__ tgam,
                        const float* __restrict__ n3g, const float* __restrict__ n3b) {
    int warp = threadIdx.x >> 5, lane = threadIdx.x & 31;
    int row = blockIdx.x * 8 + warp;
    int bidx = row*CC;
    float gamma = tgam[0];
    uint2 pv0 = ((const uint2*)(g_Pb+bidx))[lane], pv1 = ((const uint2*)(g_Pb+bidx))[lane+32];
    float pf[8];
    unpack4(pv0, pf); unpack4(pv1, pf+4);
    float4 x0 = ((const float4*)(g_X+bidx))[lane], x1 = ((const float4*)(g_X+bidx))[lane+32];
    float xn[8] = {x0.x + gamma*pf[0], x0.y + gamma*pf[1], x0.z + gamma*pf[2], x0.w + gamma*pf[3],
                   x1.x + gamma*pf[4], x1.y + gamma*pf[5], x1.z + gamma*pf[6], x1.w + gamma*pf[7]};
    float4 w0 = {xn[0],xn[1],xn[2],xn[3]}, w1 = {xn[4],xn[5],xn[6],xn[7]};
    ((float4*)(g_X+bidx))[lane] = w0; ((float4*)(g_X+bidx))[lane+32] = w1;
    float s = 0.f;
    #pragma unroll
    for (int j = 0; j < 8; j++) s += xn[j];
    float m = warpSum(s) * (1.f/CC);
    float vs = 0.f;
    #pragma unroll
    for (int j = 0; j < 8; j++) { xn[j] -= m; vs += xn[j]*xn[j]; }
    float r = rsqrtf(warpSum(vs) * (1.f/CC) + EPSI);
    float4 ga = ((const float4*)n3g)[lane], gb = ((const float4*)n3g)[lane+32];
    float4 ba = ((const float4*)n3b)[lane], bb = ((const float4*)n3b)[lane+32];
    float gf[8] = {ga.x,ga.y,ga.z,ga.w,gb.x,gb.y,gb.z,gb.w};
    float bf_[8] = {ba.x,ba.y,ba.z,ba.w,bb.x,bb.y,bb.z,bb.w};
    float o[8];
    #pragma unroll
    for (int j = 0; j < 8; j++) o[j] = xn[j]*r*gf[j] + bf_[j];
    uint2* Ob2 = (uint2*)(g_XAb + bidx);
    uint2 q0; q0.x = packbf(o[0],o[1]); q0.y = packbf(o[2],o[3]);
    uint2 q1; q1.x = packbf(o[4],o[5]); q1.y = packbf(o[6],o[7]);
    Ob2[lane] = q0; Ob2[lane+32] = q1;
}

// ---------------- K12: temporal downsample ----------------
__global__ void k_down(float* __restrict__ out) {
    int i = blockIdx.x * blockDim.x + threadIdx.x;
    const float4* X4 = (const float4*)g_X;
    const int EC4 = EE*CC/4;
    int ec = i % EC4;
    int rest = i / EC4;
    int t2 = rest % 48;
    int b  = rest / 48;
    int in0 = (b*96 + 2*t2) * EC4 + ec;
    float4 a = X4[in0], c = X4[in0 + EC4];
    float4 o;
    o.x = 0.5f*(a.x + c.x); o.y = 0.5f*(a.y + c.y);
    o.z = 0.5f*(a.z + c.z); o.w = 0.5f*(a.w + c.w);
    ((float4*)out)[i] = o;
}

// ---------------- host ----------------
extern "C" void kernel_launch(void* const* d_in, const int* in_sizes, int n_in,
                              void* d_out, int out_size) {
    const float* x    = (const float*)d_in[0];
    const float* adj  = (const float*)d_in[1];
    const float* n1g  = (const float*)d_in[2];
    const float* n1b  = (const float*)d_in[3];
    const float* swq  = (const float*)d_in[4];
    const float* swk  = (const float*)d_in[5];
    const float* swv  = (const float*)d_in[6];
    const float* swp  = (const float*)d_in[7];
    const float* sbp  = (const float*)d_in[8];
    const float* sng  = (const float*)d_in[9];
    const float* snb  = (const float*)d_in[10];
    const float* sgam = (const float*)d_in[11];
    const float* n2g  = (const float*)d_in[12];
    const float* n2b  = (const float*)d_in[13];
    const float* twq  = (const float*)d_in[14];
    const float* twk  = (const float*)d_in[15];
    const float* twv  = (const float*)d_in[16];
    const float* twp  = (const float*)d_in[17];
    const float* tbp  = (const float*)d_in[18];
    const float* tgam = (const float*)d_in[19];
    const float* n3g  = (const float*)d_in[20];
    const float* n3b  = (const float*)d_in[21];
    const float* mw1  = (const float*)d_in[22];
    const float* mb1  = (const float*)d_in[23];
    const float* mw2  = (const float*)d_in[24];
    const float* mb2  = (const float*)d_in[25];

    float *X;
    __nv_bfloat16 *XAb, *QKVb, *Ob, *Pb, *Hb, *WB;
    cudaGetSymbolAddress((void**)&X,    g_X);
    cudaGetSymbolAddress((void**)&XAb,  g_XAb);
    cudaGetSymbolAddress((void**)&QKVb, g_QKVb);
    cudaGetSymbolAddress((void**)&Ob,   g_Ob);
    cudaGetSymbolAddress((void**)&Pb,   g_Pb);
    cudaGetSymbolAddress((void**)&Hb,   g_Hb);
    cudaGetSymbolAddress((void**)&WB,   g_WB);

    cudaFuncSetAttribute(attn_mma<false>, cudaFuncAttributeMaxDynamicSharedMemorySize, ATTN_SMEM);
    cudaFuncSetAttribute(attn_mma<true>,  cudaFuncAttributeMaxDynamicSharedMemorySize, ATTN_SMEM);
    cudaFuncSetAttribute(hgemm_k<0,1>, cudaFuncAttributeMaxDynamicSharedMemorySize, HG_SMEM);
    cudaFuncSetAttribute(hgemm_k<1,1>, cudaFuncAttributeMaxDynamicSharedMemorySize, HG_SMEM);
    cudaFuncSetAttribute(hgemm_k<2,1>, cudaFuncAttributeMaxDynamicSharedMemorySize, HG_SMEM);
    cudaFuncSetAttribute(hgemm_k<3,0>, cudaFuncAttributeMaxDynamicSharedMemorySize, HG_SMEM);

    dim3 g256(2, NROWS/128);     // N=256
    dim3 g768(6, NROWS/128);     // N=768 fused QKV
    dim3 g1024(8, NROWS/128);    // N=1024

    k_wconv<<<2048, 256>>>(swq, swk, swv, swp, twq, twk, twv, twp, mw1, mw2);

    // ---- spatial block ----
    k_ln1<<<NROWS/8, 256>>>(x, n1g, n1b);
    hgemm_k<0,1><<<g768, 256, HG_SMEM>>>(XAb, WB+W_SQ, nullptr, nullptr, QKVb, NROWS, 768, CC);
    attn_mma<false><<<dim3(BB*TT, HH), 256, ATTN_SMEM>>>(QKVb, Ob, adj);
    hgemm_k<1,1><<<g256, 256, HG_SMEM>>>(Ob, WB+W_SP, sbp, nullptr, Pb, NROWS, CC, CC);
    k_fuse1<<<NROWS/8, 256>>>(sng, snb, sgam, n2g, n2b);

    // ---- temporal block ----
    hgemm_k<0,1><<<g768, 256, HG_SMEM>>>(XAb, WB+W_TQ, nullptr, nullptr, QKVb, NROWS, 768, CC);
    attn_mma<true><<<dim3(BB*EE, HH), 256, ATTN_SMEM>>>(QKVb, Ob, nullptr);
    hgemm_k<1,1><<<g256, 256, HG_SMEM>>>(Ob, WB+W_TP, tbp, nullptr, Pb, NROWS, CC, CC);
    k_fuse2<<<NROWS/8, 256>>>(tgam, n3g, n3b);

    // ---- MLP ----
    hgemm_k<2,1><<<g1024, 256, HG_SMEM>>>(XAb, WB+W_M1, mb1, nullptr, Hb, NROWS, HIDN, CC);
    hgemm_k<3,0><<<g256, 256, HG_SMEM>>>(Hb, WB+W_M2, mb2, X, X, NROWS, CC, HIDN);

    // ---- downsample ----
    k_down<<<(BB*48*EE*CC/4)/256, 256>>>((float*)d_out);

    (void)in_sizes; (void)n_in; (void)out_size;
}

// round 16
// speedup vs baseline: 1.0841x; 1.0841x over previous
#include <cuda_runtime.h>
#include <cuda_bf16.h>
#include <math.h>

#define BB 8
#define TT 96
#define EE 96
#define CC 256
#define HH 8
#define DD 32
#define HIDN 1024
#define NROWS (BB*TT*EE)   /* 73728 */
#define EPSI 1e-5f

// ---------------- scratch (static device globals; no allocations) ----------------
__device__ float g_X [NROWS*CC];            // running residual x (fp32)
__device__ float g_XA[NROWS*CC];            // xs fp32 (residual add in fuse1)
__device__ __nv_bfloat16 g_XAb[NROWS*CC];   // LN outputs, bf16 (GEMM A)
__device__ __nv_bfloat16 g_QKVb[NROWS*768]; // fused QKV output
__device__ __nv_bfloat16 g_Ob [NROWS*CC];
__device__ __nv_bfloat16 g_Pb [NROWS*CC];
__device__ __nv_bfloat16 g_Hb [NROWS*HIDN];
// transposed bf16 weights: [N][K] each
#define W_SQ 0
#define W_SK 65536
#define W_SV 131072
#define W_SP 196608
#define W_TQ 262144
#define W_TK 327680
#define W_TV 393216
#define W_TP 458752
#define W_M1 524288
#define W_M2 786432
#define W_TOT 1048576
__device__ __nv_bfloat16 g_WB[W_TOT];

__device__ __forceinline__ float warpSum(float v) {
    #pragma unroll
    for (int o = 16; o; o >>= 1) v += __shfl_xor_sync(0xffffffffu, v, o);
    return v;
}
__device__ __forceinline__ unsigned packbf(float lo, float hi) {
    unsigned r;
    asm("cvt.rn.bf16x2.f32 %0, %1, %2;" : "=r"(r) : "f"(hi), "f"(lo));
    return r;
}
__device__ __forceinline__ float2 upack2(unsigned u) {
    return __bfloat1622float2(*(__nv_bfloat162*)&u);
}
__device__ __forceinline__ void unpack4(uint2 v, float* f) {
    __nv_bfloat162* h = (__nv_bfloat162*)&v;
    float2 a = __bfloat1622float2(h[0]); float2 b = __bfloat1622float2(h[1]);
    f[0]=a.x; f[1]=a.y; f[2]=b.x; f[3]=b.y;
}

#define MMA16816(c0,c1,c2,c3,a0,a1,a2,a3,b0,b1) \
    asm volatile( \
        "mma.sync.aligned.m16n8k16.row.col.f32.bf16.bf16.f32 " \
        "{%0,%1,%2,%3},{%4,%5,%6,%7},{%8,%9},{%0,%1,%2,%3};" \
        : "+f"(c0), "+f"(c1), "+f"(c2), "+f"(c3) \
        : "r"(a0), "r"(a1), "r"(a2), "r"(a3), "r"(b0), "r"(b1))

#define LDSM4(r0,r1,r2,r3,addr) \
    asm volatile("ldmatrix.sync.aligned.m8n8.x4.shared.b16 {%0,%1,%2,%3}, [%4];" \
        : "=r"(r0), "=r"(r1), "=r"(r2), "=r"(r3) : "r"(addr))

// ---------------- K0: weights -> transposed bf16 [N][K] ----------------
__global__ void k_wconv(const float* w0, const float* w1, const float* w2, const float* w3,
                        const float* w4, const float* w5, const float* w6, const float* w7,
                        const float* w8, const float* w9) {
    const float* srcs[10] = {w0,w1,w2,w3,w4,w5,w6,w7,w8,w9};
    const int offs[10] = {W_SQ,W_SK,W_SV,W_SP,W_TQ,W_TK,W_TV,W_TP,W_M1,W_M2};
    const int KsA[10]  = {256,256,256,256,256,256,256,256,256,1024};
    const int NsA[10]  = {256,256,256,256,256,256,256,256,1024,256};
    int gid = blockIdx.x * blockDim.x + threadIdx.x;   // 524288 threads
    int e0 = gid * 2;
    int seg;
    if (e0 < W_M1) seg = e0 >> 16;
    else if (e0 < W_M2) seg = 8;
    else seg = 9;
    int Ks = KsA[seg], Ns = NsA[seg];
    int rel2 = (e0 - offs[seg]) >> 1;
    int n = rel2 % Ns;
    int k0 = (rel2 / Ns) * 2;
    const float* s = srcs[seg];
    float lo = s[k0*Ns + n], hi = s[(k0+1)*Ns + n];
    *(unsigned*)(g_WB + offs[seg] + n*Ks + k0) = packbf(lo, hi);
}

// ---------------- K1: X = x ; XA = LN(x; n1) fp32 + bf16 ----------------
__global__ void k_ln1(const float* __restrict__ x,
                      const float* __restrict__ g, const float* __restrict__ b) {
    int warp = threadIdx.x >> 5, lane = threadIdx.x & 31;
    int row = blockIdx.x * 8 + warp;
    const float4* xr = (const float4*)(x + row*CC);
    float4 a0 = xr[lane], a1 = xr[lane+32];
    float4* Xr = (float4*)(g_X + row*CC);
    Xr[lane] = a0; Xr[lane+32] = a1;
    float f[8] = {a0.x,a0.y,a0.z,a0.w,a1.x,a1.y,a1.z,a1.w};
    float s = 0.f;
    #pragma unroll
    for (int j = 0; j < 8; j++) s += f[j];
    float m = warpSum(s) * (1.f/CC);
    float vs = 0.f;
    #pragma unroll
    for (int j = 0; j < 8; j++) { f[j] -= m; vs += f[j]*f[j]; }
    float r = rsqrtf(warpSum(vs) * (1.f/CC) + EPSI);
    float4 ga = ((const float4*)g)[lane], gb = ((const float4*)g)[lane+32];
    float4 ba = ((const float4*)b)[lane], bb = ((const float4*)b)[lane+32];
    float gf[8] = {ga.x,ga.y,ga.z,ga.w,gb.x,gb.y,gb.z,gb.w};
    float bf_[8] = {ba.x,ba.y,ba.z,ba.w,bb.x,bb.y,bb.z,bb.w};
    float o[8];
    #pragma unroll
    for (int j = 0; j < 8; j++) o[j] = f[j]*r*gf[j] + bf_[j];
    float4* Or = (float4*)(g_XA + row*CC);
    float4 o0 = {o[0],o[1],o[2],o[3]}, o1 = {o[4],o[5],o[6],o[7]};
    Or[lane] = o0; Or[lane+32] = o1;
    uint2* Ob2 = (uint2*)(g_XAb + row*CC);
    uint2 p0; p0.x = packbf(o[0],o[1]); p0.y = packbf(o[2],o[3]);
    uint2 p1; p1.x = packbf(o[4],o[5]); p1.y = packbf(o[6],o[7]);
    Ob2[lane] = p0; Ob2[lane+32] = p1;
}

// ---------------- bf16 GEMM 128x128x32; round-14 structure + ldmatrix frags ----
#define T_STRIDE_U32 20   /* 40 bf16 per row (32 data + 8 pad) */

template<int EPI, int OUTBF>
__global__ void __launch_bounds__(256)
hgemm_k(const __nv_bfloat16* __restrict__ A, const __nv_bfloat16* __restrict__ Bt,
        const float* __restrict__ bias, const float* __restrict__ Res,
        void* __restrict__ Cout, int M, int N, int K) {
    __shared__ unsigned AsU[2][128 * T_STRIDE_U32];
    __shared__ unsigned BsU[2][128 * T_STRIDE_U32];

    int tid  = threadIdx.x;
    int bm   = blockIdx.y * 128, bn = blockIdx.x * 128;
    int lane = tid & 31, warp = tid >> 5;
    int wm   = (warp & 1) * 64, wn = (warp >> 1) * 32;
    int g    = lane >> 2, tig = lane & 3;

    int rowT = tid >> 2, colT = (tid & 3) * 8;   // 128x32 bf16 tile, 2 passes of 64 rows

    // ldmatrix per-lane offset (u32): m0 rows0-7/k0-7, m1 rows8-15/k0-7,
    // m2 rows0-7/k8-15, m3 rows8-15/k8-15
    int lmOff = ((lane & 7) + ((lane >> 3) & 1) * 8) * T_STRIDE_U32 + (lane >> 4) * 4;

    float acc[4][4][4];
    #pragma unroll
    for (int i = 0; i < 4; i++)
        #pragma unroll
        for (int j = 0; j < 4; j++)
            #pragma unroll
            for (int k = 0; k < 4; k++) acc[i][j][k] = 0.f;

    uint4 pa[2], pb[2];
    int kTiles = K >> 5;

    #pragma unroll
    for (int p = 0; p < 2; p++) {
        pa[p] = *(const uint4*)&A [(bm + rowT + p*64) * K + colT];
        pb[p] = *(const uint4*)&Bt[(bn + rowT + p*64) * K + colT];
    }
    #pragma unroll
    for (int p = 0; p < 2; p++) {
        unsigned* d = &AsU[0][(rowT + p*64) * T_STRIDE_U32 + (tid & 3) * 4];
        d[0] = pa[p].x; d[1] = pa[p].y; d[2] = pa[p].z; d[3] = pa[p].w;
        unsigned* e = &BsU[0][(rowT + p*64) * T_STRIDE_U32 + (tid & 3) * 4];
        e[0] = pb[p].x; e[1] = pb[p].y; e[2] = pb[p].z; e[3] = pb[p].w;
    }
    __syncthreads();

    for (int kt = 0; kt < kTiles; ++kt) {
        int buf = kt & 1;
        bool hasNext = (kt + 1 < kTiles);
        if (hasNext) {
            int kOff = (kt + 1) * 32;
            #pragma unroll
            for (int p = 0; p < 2; p++) {
                pa[p] = *(const uint4*)&A [(bm + rowT + p*64) * K + kOff + colT];
                pb[p] = *(const uint4*)&Bt[(bn + rowT + p*64) * K + kOff + colT];
            }
        }

        unsigned aBase = (unsigned)__cvta_generic_to_shared(AsU[buf]);
        unsigned bBase = (unsigned)__cvta_generic_to_shared(BsU[buf]);
        #pragma unroll
        for (int kh = 0; kh < 2; ++kh) {
            unsigned af[4][4];
            #pragma unroll
            for (int mi = 0; mi < 4; ++mi) {
                unsigned ad = aBase + (unsigned)(((wm + mi*16) * T_STRIDE_U32 + kh*8 + lmOff) * 4);
                LDSM4(af[mi][0], af[mi][1], af[mi][2], af[mi][3], ad);
            }
            unsigned bfr[4][2];
            #pragma unroll
            for (int nj = 0; nj < 2; ++nj) {
                unsigned bd = bBase + (unsigned)(((wn + nj*16) * T_STRIDE_U32 + kh*8 + lmOff) * 4);
                unsigned r0, r1, r2, r3;
                LDSM4(r0, r1, r2, r3, bd);
                bfr[nj*2][0] = r0; bfr[nj*2+1][0] = r1;
                bfr[nj*2][1] = r2; bfr[nj*2+1][1] = r3;
            }
            #pragma unroll
            for (int mi = 0; mi < 4; ++mi)
                #pragma unroll
                for (int ni = 0; ni < 4; ++ni)
                    MMA16816(acc[mi][ni][0], acc[mi][ni][1], acc[mi][ni][2], acc[mi][ni][3],
                             af[mi][0], af[mi][1], af[mi][2], af[mi][3],
                             bfr[ni][0], bfr[ni][1]);
        }

        if (hasNext) {
            int nb = buf ^ 1;
            #pragma unroll
            for (int p = 0; p < 2; p++) {
                unsigned* d = &AsU[nb][(rowT + p*64) * T_STRIDE_U32 + (tid & 3) * 4];
                d[0] = pa[p].x; d[1] = pa[p].y; d[2] = pa[p].z; d[3] = pa[p].w;
                unsigned* e = &BsU[nb][(rowT + p*64) * T_STRIDE_U32 + (tid & 3) * 4];
                e[0] = pb[p].x; e[1] = pb[p].y; e[2] = pb[p].z; e[3] = pb[p].w;
            }
            __syncthreads();
        }
    }

    #pragma unroll
    for (int mi = 0; mi < 4; ++mi) {
        int r0 = bm + wm + mi*16 + g;
        #pragma unroll
        for (int ni = 0; ni < 4; ++ni) {
            int c = bn + wn + ni*8 + tig*2;
            float v0 = acc[mi][ni][0], v1 = acc[mi][ni][1];
            float v2 = acc[mi][ni][2], v3 = acc[mi][ni][3];
            if (EPI >= 1) {
                float b0 = bias[c], b1 = bias[c+1];
                v0 += b0; v1 += b1; v2 += b0; v3 += b1;
            }
            if (EPI == 2) {
                v0 = 0.5f * v0 * (1.f + erff(v0 * 0.70710678118654752f));
                v1 = 0.5f * v1 * (1.f + erff(v1 * 0.70710678118654752f));
                v2 = 0.5f * v2 * (1.f + erff(v2 * 0.70710678118654752f));
                v3 = 0.5f * v3 * (1.f + erff(v3 * 0.70710678118654752f));
            }
            if (EPI == 3) {
                float2 ra = *(const float2*)&Res[r0 * N + c];
                float2 rb = *(const float2*)&Res[(r0 + 8) * N + c];
                v0 += ra.x; v1 += ra.y; v2 += rb.x; v3 += rb.y;
            }
            if (OUTBF) {
                unsigned* C32 = (unsigned*)Cout;
                C32[(r0 * N + c) >> 1]       = packbf(v0, v1);
                C32[((r0 + 8) * N + c) >> 1] = packbf(v2, v3);
            } else {
                float* Cf = (float*)Cout;
                float2 o0; o0.x = v0; o0.y = v1;
                float2 o1; o1.x = v2; o1.y = v3;
                *(float2*)&Cf[r0 * N + c]       = o0;
                *(float2*)&Cf[(r0 + 8) * N + c] = o1;
            }
        }
    }
}

// ---------------- attention via bf16 mma (reads fused QKV [NROWS][768]) --------
// compact smem 41.7 KB (5 CTAs/SM); warp-strip mapping with fragment reuse
#define O_SQ   0                  /* 96 x 20 u32 */
#define O_SK   1920
#define O_SVT  3840               /* 32 x 49 u32 (V transposed, stride 98 bf16) */
#define O_SS   5408               /* 96 x 52 u32 (96 bf16 data + pad) */
#define O_COL  10400              /* 32 fp32 colsums */
#define ATTN_U32 10432
#define ATTN_SMEM (ATTN_U32 * 4)  /* 41728 bytes */

template<bool TEMPORAL>
__global__ void __launch_bounds__(256)
attn_mma(const __nv_bfloat16* __restrict__ QKV, __nv_bfloat16* __restrict__ O,
         const float* __restrict__ adj) {
    extern __shared__ unsigned su[];
    unsigned* sQ  = su + O_SQ;
    unsigned* sK  = su + O_SK;
    unsigned* sVt = su + O_SVT;
    unsigned* sS  = su + O_SS;
    float* sCol   = (float*)(su + O_COL);

    int tid = threadIdx.x, lane = tid & 31, warp = tid >> 5;
    int g = lane >> 2, tig = lane & 3;
    int h = blockIdx.y;
    int row0, qstride, ostride;
    if (TEMPORAL) {
        int b = blockIdx.x / EE, e = blockIdx.x % EE;
        row0 = b*TT*EE + e;
        qstride = EE*768; ostride = EE*CC;
    } else {
        row0 = blockIdx.x * EE;
        qstride = 768; ostride = CC;
    }
    int qbase = row0*768 + h*DD;
    int obase = row0*CC  + h*DD;
    const __nv_bfloat16* Qp = QKV + qbase;
    const __nv_bfloat16* Kp = QKV + qbase + 256;
    const __nv_bfloat16* Vp = QKV + qbase + 512;

    // Q, K: 96 rows x 32 bf16 = 4 uint4 per row
    for (int i = tid; i < 96*4; i += 256) {
        int s = i >> 2, part = i & 3;
        uint4 q4 = *(const uint4*)&Qp[s*qstride + part*8];
        uint4 k4 = *(const uint4*)&Kp[s*qstride + part*8];
        unsigned* dq = &sQ[s*20 + part*4];
        dq[0]=q4.x; dq[1]=q4.y; dq[2]=q4.z; dq[3]=q4.w;
        unsigned* dk = &sK[s*20 + part*4];
        dk[0]=k4.x; dk[1]=k4.y; dk[2]=k4.z; dk[3]=k4.w;
    }
    // V transposed (u16 copy)
    const unsigned short* Vs = (const unsigned short*)Vp;
    for (int i = tid; i < 96*32; i += 256) {
        int s = i >> 5, d = i & 31;
        ((unsigned short*)sVt)[d*98 + s] = Vs[s*qstride + d];
    }
    __syncthreads();

    // spatial: fp32 column sums of V from smem (lane = d, stride-49 rows: conflict-free)
    if (!TEMPORAL && tid < 32) {
        const unsigned* vrow = &sVt[tid*49];
        float cs = 0.f;
        #pragma unroll 8
        for (int s2 = 0; s2 < 48; s2++) {
            float2 v = upack2(vrow[s2]);
            cs += v.x + v.y;
        }
        sCol[tid] = cs;
    }

    // S = Q K^T : warp w<6 owns full m16 x n96 strip; A fragments loaded ONCE
    if (warp < 6) {
        int m0 = warp * 16;
        int r0 = m0 + g, r1 = m0 + g + 8;
        unsigned aS[2][4];
        #pragma unroll
        for (int kh = 0; kh < 2; kh++) {
            const unsigned* p0 = &sQ[r0*20 + kh*8 + tig];
            const unsigned* p1 = &sQ[r1*20 + kh*8 + tig];
            aS[kh][0] = p0[0]; aS[kh][1] = p1[0];
            aS[kh][2] = p0[4]; aS[kh][3] = p1[4];
        }
        #pragma unroll
        for (int ni = 0; ni < 12; ni++) {
            int n0 = ni*8;
            float c0 = 0.f, c1 = 0.f, c2 = 0.f, c3 = 0.f;
            #pragma unroll
            for (int kh = 0; kh < 2; kh++) {
                unsigned b0 = sK[(n0+g)*20 + kh*8 + tig];
                unsigned b1 = sK[(n0+g)*20 + kh*8 + tig + 4];
                MMA16816(c0, c1, c2, c3,
                         aS[kh][0], aS[kh][1], aS[kh][2], aS[kh][3], b0, b1);
            }
            int cc = n0 + tig*2;
            if (TEMPORAL) {
                const float sc = 0.17677669529663687f;  // 1/sqrt(32)
                sS[r0*52 + ni*4 + tig] = packbf(c0*sc, c1*sc);
                sS[r1*52 + ni*4 + tig] = packbf(c2*sc, c3*sc);
            } else {
                float2 a0 = *(const float2*)&adj[r0*96 + cc];
                float2 a1 = *(const float2*)&adj[r1*96 + cc];
                sS[r0*52 + ni*4 + tig] = packbf(c0*a0.x*0.5f, c1*a0.y*0.5f);
                sS[r1*52 + ni*4 + tig] = packbf(c2*a1.x*0.5f, c3*a1.y*0.5f);
            }
        }
    }
    __syncthreads();

    if (TEMPORAL) {
        // in-place softmax on bf16 sS (fp32 math)
        for (int r = warp; r < 96; r += 8) {
            unsigned* row = &sS[r*52];
            float2 f0 = upack2(row[lane]);
            float f2 = -1e30f, f3 = -1e30f;
            if (lane < 16) {
                float2 t2 = upack2(row[32 + lane]);
                f2 = t2.x; f3 = t2.y;
            }
            float mx = fmaxf(fmaxf(f0.x, f0.y), fmaxf(f2, f3));
            #pragma unroll
            for (int o = 16; o; o >>= 1) mx = fmaxf(mx, __shfl_xor_sync(0xffffffffu, mx, o));
            float e0 = expf(f0.x - mx), e1 = expf(f0.y - mx);
            float e2 = (lane < 16) ? expf(f2 - mx) : 0.f;
            float e3 = (lane < 16) ? expf(f3 - mx) : 0.f;
            float s = warpSum(e0 + e1 + e2 + e3);
            float inv = 1.f / s;
            row[lane] = packbf(e0*inv, e1*inv);
            if (lane < 16) row[32 + lane] = packbf(e2*inv, e3*inv);
        }
        __syncthreads();
    }

    // O = S V : warp w<6 owns m16 x n32; ks-outer, A loaded once/ks
    unsigned* O32 = (unsigned*)O;
    if (warp < 6) {
        int m0 = warp * 16;
        int r0 = m0 + g, r1 = m0 + g + 8;
        float c[4][4];
        #pragma unroll
        for (int ni = 0; ni < 4; ni++)
            #pragma unroll
            for (int j = 0; j < 4; j++) c[ni][j] = 0.f;
        #pragma unroll
        for (int ks = 0; ks < 6; ks++) {
            unsigned a0 = sS[r0*52 + ks*8 + tig];
            unsigned a1 = sS[r1*52 + ks*8 + tig];
            unsigned a2 = sS[r0*52 + ks*8 + tig + 4];
            unsigned a3 = sS[r1*52 + ks*8 + tig + 4];
            #pragma unroll
            for (int ni = 0; ni < 4; ni++) {
                unsigned b0 = sVt[(ni*8+g)*49 + ks*8 + tig];
                unsigned b1 = sVt[(ni*8+g)*49 + ks*8 + tig + 4];
                MMA16816(c[ni][0], c[ni][1], c[ni][2], c[ni][3], a0, a1, a2, a3, b0, b1);
            }
        }
        #pragma unroll
        for (int ni = 0; ni < 4; ni++) {
            int cc = ni*8 + tig*2;
            float v0 = c[ni][0], v1 = c[ni][1], v2 = c[ni][2], v3 = c[ni][3];
            if (!TEMPORAL) {
                float ca = 0.5f * sCol[cc], cb = 0.5f * sCol[cc+1];
                v0 += ca; v1 += cb; v2 += ca; v3 += cb;
            }
            O32[(obase + r0*ostride + cc) >> 1] = packbf(v0, v1);
            O32[(obase + r1*ostride + cc) >> 1] = packbf(v2, v3);
        }
    }
}

// ---------------- K5: p=LN(Pb;s_n); x += xs + s_gamma*p; XAb = LN(x; n2) --------
__global__ void k_fuse1(const float* __restrict__ sng, const float* __restrict__ snb,
                        const float* __restrict__ sgam,
                        const float* __restrict__ n2g, const float* __restrict__ n2b) {
    int warp = threadIdx.x >> 5, lane = threadIdx.x & 31;
    int row = blockIdx.x * 8 + warp;
    int bidx = row*CC;
    uint2 pv0 = ((const uint2*)(g_Pb+bidx))[lane], pv1 = ((const uint2*)(g_Pb+bidx))[lane+32];
    float pf[8];
    unpack4(pv0, pf); unpack4(pv1, pf+4);
    float s = 0.f;
    #pragma unroll
    for (int j = 0; j < 8; j++) s += pf[j];
    float m1 = warpSum(s) * (1.f/CC);
    float vs = 0.f;
    #pragma unroll
    for (int j = 0; j < 8; j++) { pf[j] -= m1; vs += pf[j]*pf[j]; }
    float r1 = rsqrtf(warpSum(vs) * (1.f/CC) + EPSI);
    float4 ga = ((const float4*)sng)[lane], gb = ((const float4*)sng)[lane+32];
    float4 ba = ((const float4*)snb)[lane], bb = ((const float4*)snb)[lane+32];
    float gf[8] = {ga.x,ga.y,ga.z,ga.w,gb.x,gb.y,gb.z,gb.w};
    float bf_[8] = {ba.x,ba.y,ba.z,ba.w,bb.x,bb.y,bb.z,bb.w};
    float gamma = sgam[0];
    float4 x0 = ((const float4*)(g_X+bidx))[lane],  x1 = ((const float4*)(g_X+bidx))[lane+32];
    float4 s0 = ((const float4*)(g_XA+bidx))[lane], s1 = ((const float4*)(g_XA+bidx))[lane+32];
    float xf[8] = {x0.x,x0.y,x0.z,x0.w,x1.x,x1.y,x1.z,x1.w};
    float sf[8] = {s0.x,s0.y,s0.z,s0.w,s1.x,s1.y,s1.z,s1.w};
    float xn[8];
    #pragma unroll
    for (int j = 0; j < 8; j++)
        xn[j] = xf[j] + sf[j] + gamma * (pf[j]*r1*gf[j] + bf_[j]);
    float4 w0 = {xn[0],xn[1],xn[2],xn[3]}, w1 = {xn[4],xn[5],xn[6],xn[7]};
    ((float4*)(g_X+bidx))[lane] = w0; ((float4*)(g_X+bidx))[lane+32] = w1;
    float s2 = 0.f;
    #pragma unroll
    for (int j = 0; j < 8; j++) s2 += xn[j];
    float m2 = warpSum(s2) * (1.f/CC);
    float vs2 = 0.f;
    #pragma unroll
    for (int j = 0; j < 8; j++) { xn[j] -= m2; vs2 += xn[j]*xn[j]; }
    float r2 = rsqrtf(warpSum(vs2) * (1.f/CC) + EPSI);
    float4 g2a = ((const float4*)n2g)[lane], g2b = ((const float4*)n2g)[lane+32];
    float4 b2a = ((const float4*)n2b)[lane], b2b = ((const float4*)n2b)[lane+32];
    float g2f[8] = {g2a.x,g2a.y,g2a.z,g2a.w,g2b.x,g2b.y,g2b.z,g2b.w};
    float b2f[8] = {b2a.x,b2a.y,b2a.z,b2a.w,b2b.x,b2b.y,b2b.z,b2b.w};
    float o[8];
    #pragma unroll
    for (int j = 0; j < 8; j++) o[j] = xn[j]*r2*g2f[j] + b2f[j];
    uint2* Ob2 = (uint2*)(g_XAb + bidx);
    uint2 q0; q0.x = packbf(o[0],o[1]); q0.y = packbf(o[2],o[3]);
    uint2 q1; q1.x = packbf(o[4],o[5]); q1.y = packbf(o[6],o[7]);
    Ob2[lane] = q0; Ob2[lane+32] = q1;
}

// ---------------- K9: x += t_gamma*Pb; XAb = LN(x; n3) ----------------
__global__ void k_fuse2(const float* __restrict__ tgam,
                        const float* __restrict__ n3g, const float* __restrict__ n3b) {
    int warp = threadIdx.x >> 5, lane = threadIdx.x & 31;
    int row = blockIdx.x * 8 + warp;
    int bidx = row*CC;
    float gamma = tgam[0];
    uint2 pv0 = ((const uint2*)(g_Pb+bidx))[lane], pv1 = ((const uint2*)(g_Pb+bidx))[lane+32];
    float pf[8];
    unpack4(pv0, pf); unpack4(pv1, pf+4);
    float4 x0 = ((const float4*)(g_X+bidx))[lane], x1 = ((const float4*)(g_X+bidx))[lane+32];
    float xn[8] = {x0.x + gamma*pf[0], x0.y + gamma*pf[1], x0.z + gamma*pf[2], x0.w + gamma*pf[3],
                   x1.x + gamma*pf[4], x1.y + gamma*pf[5], x1.z + gamma*pf[6], x1.w + gamma*pf[7]};
    float4 w0 = {xn[0],xn[1],xn[2],xn[3]}, w1 = {xn[4],xn[5],xn[6],xn[7]};
    ((float4*)(g_X+bidx))[lane] = w0; ((float4*)(g_X+bidx))[lane+32] = w1;
    float s = 0.f;
    #pragma unroll
    for (int j = 0; j < 8; j++) s += xn[j];
    float m = warpSum(s) * (1.f/CC);
    float vs = 0.f;
    #pragma unroll
    for (int j = 0; j < 8; j++) { xn[j] -= m; vs += xn[j]*xn[j]; }
    float r = rsqrtf(warpSum(vs) * (1.f/CC) + EPSI);
    float4 ga = ((const float4*)n3g)[lane], gb = ((const float4*)n3g)[lane+32];
    float4 ba = ((const float4*)n3b)[lane], bb = ((const float4*)n3b)[lane+32];
    float gf[8] = {ga.x,ga.y,ga.z,ga.w,gb.x,gb.y,gb.z,gb.w};
    float bf_[8] = {ba.x,ba.y,ba.z,ba.w,bb.x,bb.y,bb.z,bb.w};
    float o[8];
    #pragma unroll
    for (int j = 0; j < 8; j++) o[j] = xn[j]*r*gf[j] + bf_[j];
    uint2* Ob2 = (uint2*)(g_XAb + bidx);
    uint2 q0; q0.x = packbf(o[0],o[1]); q0.y = packbf(o[2],o[3]);
    uint2 q1; q1.x = packbf(o[4],o[5]); q1.y = packbf(o[6],o[7]);
    Ob2[lane] = q0; Ob2[lane+32] = q1;
}

// ---------------- K12: temporal downsample ----------------
__global__ void k_down(float* __restrict__ out) {
    int i = blockIdx.x * blockDim.x + threadIdx.x;
    const float4* X4 = (const float4*)g_X;
    const int EC4 = EE*CC/4;
    int ec = i % EC4;
    int rest = i / EC4;
    int t2 = rest % 48;
    int b  = rest / 48;
    int in0 = (b*96 + 2*t2) * EC4 + ec;
    float4 a = X4[in0], c = X4[in0 + EC4];
    float4 o;
    o.x = 0.5f*(a.x + c.x); o.y = 0.5f*(a.y + c.y);
    o.z = 0.5f*(a.z + c.z); o.w = 0.5f*(a.w + c.w);
    ((float4*)out)[i] = o;
}

// ---------------- host ----------------
extern "C" void kernel_launch(void* const* d_in, const int* in_sizes, int n_in,
                              void* d_out, int out_size) {
    const float* x    = (const float*)d_in[0];
    const float* adj  = (const float*)d_in[1];
    const float* n1g  = (const float*)d_in[2];
    const float* n1b  = (const float*)d_in[3];
    const float* swq  = (const float*)d_in[4];
    const float* swk  = (const float*)d_in[5];
    const float* swv  = (const float*)d_in[6];
    const float* swp  = (const float*)d_in[7];
    const float* sbp  = (const float*)d_in[8];
    const float* sng  = (const float*)d_in[9];
    const float* snb  = (const float*)d_in[10];
    const float* sgam = (const float*)d_in[11];
    const float* n2g  = (const float*)d_in[12];
    const float* n2b  = (const float*)d_in[13];
    const float* twq  = (const float*)d_in[14];
    const float* twk  = (const float*)d_in[15];
    const float* twv  = (const float*)d_in[16];
    const float* twp  = (const float*)d_in[17];
    const float* tbp  = (const float*)d_in[18];
    const float* tgam = (const float*)d_in[19];
    const float* n3g  = (const float*)d_in[20];
    const float* n3b  = (const float*)d_in[21];
    const float* mw1  = (const float*)d_in[22];
    const float* mb1  = (const float*)d_in[23];
    const float* mw2  = (const float*)d_in[24];
    const float* mb2  = (const float*)d_in[25];

    float *X;
    __nv_bfloat16 *XAb, *QKVb, *Ob, *Pb, *Hb, *WB;
    cudaGetSymbolAddress((void**)&X,    g_X);
    cudaGetSymbolAddress((void**)&XAb,  g_XAb);
    cudaGetSymbolAddress((void**)&QKVb, g_QKVb);
    cudaGetSymbolAddress((void**)&Ob,   g_Ob);
    cudaGetSymbolAddress((void**)&Pb,   g_Pb);
    cudaGetSymbolAddress((void**)&Hb,   g_Hb);
    cudaGetSymbolAddress((void**)&WB,   g_WB);

    cudaFuncSetAttribute(attn_mma<false>, cudaFuncAttributeMaxDynamicSharedMemorySize, ATTN_SMEM);
    cudaFuncSetAttribute(attn_mma<true>,  cudaFuncAttributeMaxDynamicSharedMemorySize, ATTN_SMEM);

    dim3 g256(2, NROWS/128);     // N=256
    dim3 g768(6, NROWS/128);     // N=768 fused QKV
    dim3 g1024(8, NROWS/128);    // N=1024

    k_wconv<<<2048, 256>>>(swq, swk, swv, swp, twq, twk, twv, twp, mw1, mw2);

    // ---- spatial block ----
    k_ln1<<<NROWS/8, 256>>>(x, n1g, n1b);
    hgemm_k<0,1><<<g768, 256>>>(XAb, WB+W_SQ, nullptr, nullptr, QKVb, NROWS, 768, CC);
    attn_mma<false><<<dim3(BB*TT, HH), 256, ATTN_SMEM>>>(QKVb, Ob, adj);
    hgemm_k<1,1><<<g256, 256>>>(Ob, WB+W_SP, sbp, nullptr, Pb, NROWS, CC, CC);
    k_fuse1<<<NROWS/8, 256>>>(sng, snb, sgam, n2g, n2b);

    // ---- temporal block ----
    hgemm_k<0,1><<<g768, 256>>>(XAb, WB+W_TQ, nullptr, nullptr, QKVb, NROWS, 768, CC);
    attn_mma<true><<<dim3(BB*EE, HH), 256, ATTN_SMEM>>>(QKVb, Ob, nullptr);
    hgemm_k<1,1><<<g256, 256>>>(Ob, WB+W_TP, tbp, nullptr, Pb, NROWS, CC, CC);
    k_fuse2<<<NROWS/8, 256>>>(tgam, n3g, n3b);

    // ---- MLP ----
    hgemm_k<2,1><<<g1024, 256>>>(XAb, WB+W_M1, mb1, nullptr, Hb, NROWS, HIDN, CC);
    hgemm_k<3,0><<<g256, 256>>>(Hb, WB+W_M2, mb2, X, X, NROWS, CC, HIDN);

    // ---- downsample ----
    k_down<<<(BB*48*EE*CC/4)/256, 256>>>((float*)d_out);

    (void)in_sizes; (void)n_in; (void)out_size;
}

// round 17
// speedup vs baseline: 1.1199x; 1.0330x over previous
#include <cuda_runtime.h>
#include <cuda_bf16.h>
#include <math.h>

#define BB 8
#define TT 96
#define EE 96
#define CC 256
#define HH 8
#define DD 32
#define HIDN 1024
#define NROWS (BB*TT*EE)   /* 73728 */
#define EPSI 1e-5f

// ---------------- scratch (static device globals; no allocations) ----------------
__device__ float g_X [NROWS*CC];            // running residual x (fp32)
__device__ float g_XA[NROWS*CC];            // xs fp32 (residual add in fuse1)
__device__ __nv_bfloat16 g_XAb[NROWS*CC];   // LN outputs, bf16 (GEMM A)
__device__ __nv_bfloat16 g_QKVb[NROWS*768]; // fused QKV output
__device__ __nv_bfloat16 g_Ob [NROWS*CC];
__device__ __nv_bfloat16 g_Pb [NROWS*CC];
__device__ __nv_bfloat16 g_Hb [NROWS*HIDN];
// transposed bf16 weights: [N][K] each
#define W_SQ 0
#define W_SK 65536
#define W_SV 131072
#define W_SP 196608
#define W_TQ 262144
#define W_TK 327680
#define W_TV 393216
#define W_TP 458752
#define W_M1 524288
#define W_M2 786432
#define W_TOT 1048576
__device__ __nv_bfloat16 g_WB[W_TOT];

__device__ __forceinline__ float warpSum(float v) {
    #pragma unroll
    for (int o = 16; o; o >>= 1) v += __shfl_xor_sync(0xffffffffu, v, o);
    return v;
}
__device__ __forceinline__ unsigned packbf(float lo, float hi) {
    unsigned r;
    asm("cvt.rn.bf16x2.f32 %0, %1, %2;" : "=r"(r) : "f"(hi), "f"(lo));
    return r;
}
__device__ __forceinline__ float2 upack2(unsigned u) {
    return __bfloat1622float2(*(__nv_bfloat162*)&u);
}
__device__ __forceinline__ void unpack4(uint2 v, float* f) {
    __nv_bfloat162* h = (__nv_bfloat162*)&v;
    float2 a = __bfloat1622float2(h[0]); float2 b = __bfloat1622float2(h[1]);
    f[0]=a.x; f[1]=a.y; f[2]=b.x; f[3]=b.y;
}

#define MMA16816(c0,c1,c2,c3,a0,a1,a2,a3,b0,b1) \
    asm volatile( \
        "mma.sync.aligned.m16n8k16.row.col.f32.bf16.bf16.f32 " \
        "{%0,%1,%2,%3},{%4,%5,%6,%7},{%8,%9},{%0,%1,%2,%3};" \
        : "+f"(c0), "+f"(c1), "+f"(c2), "+f"(c3) \
        : "r"(a0), "r"(a1), "r"(a2), "r"(a3), "r"(b0), "r"(b1))

#define LDSM4(r0,r1,r2,r3,addr) \
    asm volatile("ldmatrix.sync.aligned.m8n8.x4.shared.b16 {%0,%1,%2,%3}, [%4];" \
        : "=r"(r0), "=r"(r1), "=r"(r2), "=r"(r3) : "r"(addr))

// ---------------- K0: weights -> transposed bf16 [N][K] ----------------
__global__ void k_wconv(const float* w0, const float* w1, const float* w2, const float* w3,
                        const float* w4, const float* w5, const float* w6, const float* w7,
                        const float* w8, const float* w9) {
    const float* srcs[10] = {w0,w1,w2,w3,w4,w5,w6,w7,w8,w9};
    const int offs[10] = {W_SQ,W_SK,W_SV,W_SP,W_TQ,W_TK,W_TV,W_TP,W_M1,W_M2};
    const int KsA[10]  = {256,256,256,256,256,256,256,256,256,1024};
    const int NsA[10]  = {256,256,256,256,256,256,256,256,1024,256};
    int gid = blockIdx.x * blockDim.x + threadIdx.x;   // 524288 threads
    int e0 = gid * 2;
    int seg;
    if (e0 < W_M1) seg = e0 >> 16;
    else if (e0 < W_M2) seg = 8;
    else seg = 9;
    int Ks = KsA[seg], Ns = NsA[seg];
    int rel2 = (e0 - offs[seg]) >> 1;
    int n = rel2 % Ns;
    int k0 = (rel2 / Ns) * 2;
    const float* s = srcs[seg];
    float lo = s[k0*Ns + n], hi = s[(k0+1)*Ns + n];
    *(unsigned*)(g_WB + offs[seg] + n*Ks + k0) = packbf(lo, hi);
}

// ---------------- K1: X = x ; XA = LN(x; n1) fp32 + bf16 ----------------
__global__ void k_ln1(const float* __restrict__ x,
                      const float* __restrict__ g, const float* __restrict__ b) {
    int warp = threadIdx.x >> 5, lane = threadIdx.x & 31;
    int row = blockIdx.x * 8 + warp;
    const float4* xr = (const float4*)(x + row*CC);
    float4 a0 = xr[lane], a1 = xr[lane+32];
    float4* Xr = (float4*)(g_X + row*CC);
    Xr[lane] = a0; Xr[lane+32] = a1;
    float f[8] = {a0.x,a0.y,a0.z,a0.w,a1.x,a1.y,a1.z,a1.w};
    float s = 0.f;
    #pragma unroll
    for (int j = 0; j < 8; j++) s += f[j];
    float m = warpSum(s) * (1.f/CC);
    float vs = 0.f;
    #pragma unroll
    for (int j = 0; j < 8; j++) { f[j] -= m; vs += f[j]*f[j]; }
    float r = rsqrtf(warpSum(vs) * (1.f/CC) + EPSI);
    float4 ga = ((const float4*)g)[lane], gb = ((const float4*)g)[lane+32];
    float4 ba = ((const float4*)b)[lane], bb = ((const float4*)b)[lane+32];
    float gf[8] = {ga.x,ga.y,ga.z,ga.w,gb.x,gb.y,gb.z,gb.w};
    float bf_[8] = {ba.x,ba.y,ba.z,ba.w,bb.x,bb.y,bb.z,bb.w};
    float o[8];
    #pragma unroll
    for (int j = 0; j < 8; j++) o[j] = f[j]*r*gf[j] + bf_[j];
    float4* Or = (float4*)(g_XA + row*CC);
    float4 o0 = {o[0],o[1],o[2],o[3]}, o1 = {o[4],o[5],o[6],o[7]};
    Or[lane] = o0; Or[lane+32] = o1;
    uint2* Ob2 = (uint2*)(g_XAb + row*CC);
    uint2 p0; p0.x = packbf(o[0],o[1]); p0.y = packbf(o[2],o[3]);
    uint2 p1; p1.x = packbf(o[4],o[5]); p1.y = packbf(o[6],o[7]);
    Ob2[lane] = p0; Ob2[lane+32] = p1;
}

// ---------------- bf16 GEMM 128x128x32; round-14 structure + ldmatrix frags ----
#define T_STRIDE_U32 20   /* 40 bf16 per row (32 data + 8 pad) */

template<int EPI, int OUTBF>
__global__ void __launch_bounds__(256)
hgemm_k(const __nv_bfloat16* __restrict__ A, const __nv_bfloat16* __restrict__ Bt,
        const float* __restrict__ bias, const float* __restrict__ Res,
        void* __restrict__ Cout, int M, int N, int K) {
    __shared__ unsigned AsU[2][128 * T_STRIDE_U32];
    __shared__ unsigned BsU[2][128 * T_STRIDE_U32];

    int tid  = threadIdx.x;
    int bm   = blockIdx.y * 128, bn = blockIdx.x * 128;
    int lane = tid & 31, warp = tid >> 5;
    int wm   = (warp & 1) * 64, wn = (warp >> 1) * 32;
    int g    = lane >> 2, tig = lane & 3;

    int rowT = tid >> 2, colT = (tid & 3) * 8;

    int lmOff = ((lane & 7) + ((lane >> 3) & 1) * 8) * T_STRIDE_U32 + (lane >> 4) * 4;

    float acc[4][4][4];
    #pragma unroll
    for (int i = 0; i < 4; i++)
        #pragma unroll
        for (int j = 0; j < 4; j++)
            #pragma unroll
            for (int k = 0; k < 4; k++) acc[i][j][k] = 0.f;

    uint4 pa[2], pb[2];
    int kTiles = K >> 5;

    #pragma unroll
    for (int p = 0; p < 2; p++) {
        pa[p] = *(const uint4*)&A [(bm + rowT + p*64) * K + colT];
        pb[p] = *(const uint4*)&Bt[(bn + rowT + p*64) * K + colT];
    }
    #pragma unroll
    for (int p = 0; p < 2; p++) {
        unsigned* d = &AsU[0][(rowT + p*64) * T_STRIDE_U32 + (tid & 3) * 4];
        d[0] = pa[p].x; d[1] = pa[p].y; d[2] = pa[p].z; d[3] = pa[p].w;
        unsigned* e = &BsU[0][(rowT + p*64) * T_STRIDE_U32 + (tid & 3) * 4];
        e[0] = pb[p].x; e[1] = pb[p].y; e[2] = pb[p].z; e[3] = pb[p].w;
    }
    __syncthreads();

    for (int kt = 0; kt < kTiles; ++kt) {
        int buf = kt & 1;
        bool hasNext = (kt + 1 < kTiles);
        if (hasNext) {
            int kOff = (kt + 1) * 32;
            #pragma unroll
            for (int p = 0; p < 2; p++) {
                pa[p] = *(const uint4*)&A [(bm + rowT + p*64) * K + kOff + colT];
                pb[p] = *(const uint4*)&Bt[(bn + rowT + p*64) * K + kOff + colT];
            }
        }

        unsigned aBase = (unsigned)__cvta_generic_to_shared(AsU[buf]);
        unsigned bBase = (unsigned)__cvta_generic_to_shared(BsU[buf]);
        #pragma unroll
        for (int kh = 0; kh < 2; ++kh) {
            unsigned af[4][4];
            #pragma unroll
            for (int mi = 0; mi < 4; ++mi) {
                unsigned ad = aBase + (unsigned)(((wm + mi*16) * T_STRIDE_U32 + kh*8 + lmOff) * 4);
                LDSM4(af[mi][0], af[mi][1], af[mi][2], af[mi][3], ad);
            }
            unsigned bfr[4][2];
            #pragma unroll
            for (int nj = 0; nj < 2; ++nj) {
                unsigned bd = bBase + (unsigned)(((wn + nj*16) * T_STRIDE_U32 + kh*8 + lmOff) * 4);
                unsigned r0, r1, r2, r3;
                LDSM4(r0, r1, r2, r3, bd);
                bfr[nj*2][0] = r0; bfr[nj*2+1][0] = r1;
                bfr[nj*2][1] = r2; bfr[nj*2+1][1] = r3;
            }
            #pragma unroll
            for (int mi = 0; mi < 4; ++mi)
                #pragma unroll
                for (int ni = 0; ni < 4; ++ni)
                    MMA16816(acc[mi][ni][0], acc[mi][ni][1], acc[mi][ni][2], acc[mi][ni][3],
                             af[mi][0], af[mi][1], af[mi][2], af[mi][3],
                             bfr[ni][0], bfr[ni][1]);
        }

        if (hasNext) {
            int nb = buf ^ 1;
            #pragma unroll
            for (int p = 0; p < 2; p++) {
                unsigned* d = &AsU[nb][(rowT + p*64) * T_STRIDE_U32 + (tid & 3) * 4];
                d[0] = pa[p].x; d[1] = pa[p].y; d[2] = pa[p].z; d[3] = pa[p].w;
                unsigned* e = &BsU[nb][(rowT + p*64) * T_STRIDE_U32 + (tid & 3) * 4];
                e[0] = pb[p].x; e[1] = pb[p].y; e[2] = pb[p].z; e[3] = pb[p].w;
            }
            __syncthreads();
        }
    }

    #pragma unroll
    for (int mi = 0; mi < 4; ++mi) {
        int r0 = bm + wm + mi*16 + g;
        #pragma unroll
        for (int ni = 0; ni < 4; ++ni) {
            int c = bn + wn + ni*8 + tig*2;
            float v0 = acc[mi][ni][0], v1 = acc[mi][ni][1];
            float v2 = acc[mi][ni][2], v3 = acc[mi][ni][3];
            if (EPI >= 1) {
                float b0 = bias[c], b1 = bias[c+1];
                v0 += b0; v1 += b1; v2 += b0; v3 += b1;
            }
            if (EPI == 2) {
                v0 = 0.5f * v0 * (1.f + erff(v0 * 0.70710678118654752f));
                v1 = 0.5f * v1 * (1.f + erff(v1 * 0.70710678118654752f));
                v2 = 0.5f * v2 * (1.f + erff(v2 * 0.70710678118654752f));
                v3 = 0.5f * v3 * (1.f + erff(v3 * 0.70710678118654752f));
            }
            if (EPI == 3) {
                float2 ra = *(const float2*)&Res[r0 * N + c];
                float2 rb = *(const float2*)&Res[(r0 + 8) * N + c];
                v0 += ra.x; v1 += ra.y; v2 += rb.x; v3 += rb.y;
            }
            if (OUTBF) {
                unsigned* C32 = (unsigned*)Cout;
                C32[(r0 * N + c) >> 1]       = packbf(v0, v1);
                C32[((r0 + 8) * N + c) >> 1] = packbf(v2, v3);
            } else {
                float* Cf = (float*)Cout;
                float2 o0; o0.x = v0; o0.y = v1;
                float2 o1; o1.x = v2; o1.y = v3;
                *(float2*)&Cf[r0 * N + c]       = o0;
                *(float2*)&Cf[(r0 + 8) * N + c] = o1;
            }
        }
    }
}

// ---------------- attention: barrier-free after load; warp-owned strips --------
#define O_SQ   0                  /* 96 x 20 u32 */
#define O_SK   1920
#define O_SVT  3840               /* 32 x 49 u32 (V transposed, stride 98 bf16) */
#define O_SS   5408               /* 96 x 52 u32 */
#define ATTN_U32 10400
#define ATTN_SMEM (ATTN_U32 * 4)  /* 41600 bytes */

template<bool TEMPORAL>
__global__ void __launch_bounds__(256)
attn_mma(const __nv_bfloat16* __restrict__ QKV, __nv_bfloat16* __restrict__ O,
         const float* __restrict__ adj) {
    extern __shared__ unsigned su[];
    unsigned* sQ  = su + O_SQ;
    unsigned* sK  = su + O_SK;
    unsigned* sVt = su + O_SVT;
    unsigned* sS  = su + O_SS;

    int tid = threadIdx.x, lane = tid & 31, warp = tid >> 5;
    int g = lane >> 2, tig = lane & 3;
    int h = blockIdx.y;
    int row0, qstride, ostride;
    if (TEMPORAL) {
        int b = blockIdx.x / EE, e = blockIdx.x % EE;
        row0 = b*TT*EE + e;
        qstride = EE*768; ostride = EE*CC;
    } else {
        row0 = blockIdx.x * EE;
        qstride = 768; ostride = CC;
    }
    int qbase = row0*768 + h*DD;
    int obase = row0*CC  + h*DD;
    const __nv_bfloat16* Qp = QKV + qbase;
    const __nv_bfloat16* Kp = QKV + qbase + 256;
    const __nv_bfloat16* Vp = QKV + qbase + 512;

    // Q, K: 96 rows x 32 bf16 = 4 uint4 per row
    for (int i = tid; i < 96*4; i += 256) {
        int s = i >> 2, part = i & 3;
        uint4 q4 = *(const uint4*)&Qp[s*qstride + part*8];
        uint4 k4 = *(const uint4*)&Kp[s*qstride + part*8];
        unsigned* dq = &sQ[s*20 + part*4];
        dq[0]=q4.x; dq[1]=q4.y; dq[2]=q4.z; dq[3]=q4.w;
        unsigned* dk = &sK[s*20 + part*4];
        dk[0]=k4.x; dk[1]=k4.y; dk[2]=k4.z; dk[3]=k4.w;
    }
    // V transposed: vectorized uint4 global load + u16 scatter
    {
        unsigned short* sv16 = (unsigned short*)sVt;
        for (int i = tid; i < 96*4; i += 256) {
            int s = i >> 2, part = i & 3;
            uint4 v4 = *(const uint4*)&Vp[s*qstride + part*8];
            int d0 = part*8;
            sv16[(d0+0)*98+s] = (unsigned short)(v4.x);
            sv16[(d0+1)*98+s] = (unsigned short)(v4.x >> 16);
            sv16[(d0+2)*98+s] = (unsigned short)(v4.y);
            sv16[(d0+3)*98+s] = (unsigned short)(v4.y >> 16);
            sv16[(d0+4)*98+s] = (unsigned short)(v4.z);
            sv16[(d0+5)*98+s] = (unsigned short)(v4.z >> 16);
            sv16[(d0+6)*98+s] = (unsigned short)(v4.w);
            sv16[(d0+7)*98+s] = (unsigned short)(v4.w >> 16);
        }
    }
    __syncthreads();

    if (warp >= 6) return;   // no block barriers after this point

    int m0 = warp * 16;
    int r0 = m0 + g, r1 = m0 + g + 8;

    // spatial: per-warp colsum register (lane = head dim d), same accumulate order
    float csLane = 0.f;
    if (!TEMPORAL) {
        const unsigned* vrow = &sVt[lane*49];
        #pragma unroll 8
        for (int s2 = 0; s2 < 48; s2++) {
            float2 v = upack2(vrow[s2]);
            csLane += v.x + v.y;
        }
    }

    // S = Q K^T : warp owns m16 x n96 strip; A fragments loaded once
    {
        unsigned aS[2][4];
        #pragma unroll
        for (int kh = 0; kh < 2; kh++) {
            const unsigned* p0 = &sQ[r0*20 + kh*8 + tig];
            const unsigned* p1 = &sQ[r1*20 + kh*8 + tig];
            aS[kh][0] = p0[0]; aS[kh][1] = p1[0];
            aS[kh][2] = p0[4]; aS[kh][3] = p1[4];
        }
        #pragma unroll
        for (int ni = 0; ni < 12; ni++) {
            int n0 = ni*8;
            float c0 = 0.f, c1 = 0.f, c2 = 0.f, c3 = 0.f;
            #pragma unroll
            for (int kh = 0; kh < 2; kh++) {
                unsigned b0 = sK[(n0+g)*20 + kh*8 + tig];
                unsigned b1 = sK[(n0+g)*20 + kh*8 + tig + 4];
                MMA16816(c0, c1, c2, c3,
                         aS[kh][0], aS[kh][1], aS[kh][2], aS[kh][3], b0, b1);
            }
            int cc = n0 + tig*2;
            if (TEMPORAL) {
                const float sc = 0.17677669529663687f;  // 1/sqrt(32)
                sS[r0*52 + ni*4 + tig] = packbf(c0*sc, c1*sc);
                sS[r1*52 + ni*4 + tig] = packbf(c2*sc, c3*sc);
            } else {
                float2 a0 = *(const float2*)&adj[r0*96 + cc];
                float2 a1 = *(const float2*)&adj[r1*96 + cc];
                sS[r0*52 + ni*4 + tig] = packbf(c0*a0.x*0.5f, c1*a0.y*0.5f);
                sS[r1*52 + ni*4 + tig] = packbf(c2*a1.x*0.5f, c3*a1.y*0.5f);
            }
        }
    }
    __syncwarp();

    if (TEMPORAL) {
        // in-place softmax on this warp's own 16 rows
        for (int r = m0; r < m0 + 16; r++) {
            unsigned* row = &sS[r*52];
            float2 f0 = upack2(row[lane]);
            float f2 = -1e30f, f3 = -1e30f;
            if (lane < 16) {
                float2 t2 = upack2(row[32 + lane]);
                f2 = t2.x; f3 = t2.y;
            }
            float mx = fmaxf(fmaxf(f0.x, f0.y), fmaxf(f2, f3));
            #pragma unroll
            for (int o = 16; o; o >>= 1) mx = fmaxf(mx, __shfl_xor_sync(0xffffffffu, mx, o));
            float e0 = expf(f0.x - mx), e1 = expf(f0.y - mx);
            float e2 = (lane < 16) ? expf(f2 - mx) : 0.f;
            float e3 = (lane < 16) ? expf(f3 - mx) : 0.f;
            float s = warpSum(e0 + e1 + e2 + e3);
            float inv = 1.f / s;
            row[lane] = packbf(e0*inv, e1*inv);
            if (lane < 16) row[32 + lane] = packbf(e2*inv, e3*inv);
        }
        __syncwarp();
    }

    // O = S V : warp owns m16 x n32; ks-outer, A loaded once/ks
    unsigned* O32 = (unsigned*)O;
    {
        float c[4][4];
        #pragma unroll
        for (int ni = 0; ni < 4; ni++)
            #pragma unroll
            for (int j = 0; j < 4; j++) c[ni][j] = 0.f;
        #pragma unroll
        for (int ks = 0; ks < 6; ks++) {
            unsigned a0 = sS[r0*52 + ks*8 + tig];
            unsigned a1 = sS[r1*52 + ks*8 + tig];
            unsigned a2 = sS[r0*52 + ks*8 + tig + 4];
            unsigned a3 = sS[r1*52 + ks*8 + tig + 4];
            #pragma unroll
            for (int ni = 0; ni < 4; ni++) {
                unsigned b0 = sVt[(ni*8+g)*49 + ks*8 + tig];
                unsigned b1 = sVt[(ni*8+g)*49 + ks*8 + tig + 4];
                MMA16816(c[ni][0], c[ni][1], c[ni][2], c[ni][3], a0, a1, a2, a3, b0, b1);
            }
        }
        #pragma unroll
        for (int ni = 0; ni < 4; ni++) {
            int cc = ni*8 + tig*2;
            float v0 = c[ni][0], v1 = c[ni][1], v2 = c[ni][2], v3 = c[ni][3];
            if (!TEMPORAL) {
                float ca = 0.5f * __shfl_sync(0xffffffffu, csLane, cc);
                float cb = 0.5f * __shfl_sync(0xffffffffu, csLane, cc + 1);
                v0 += ca; v1 += cb; v2 += ca; v3 += cb;
            }
            O32[(obase + r0*ostride + cc) >> 1] = packbf(v0, v1);
            O32[(obase + r1*ostride + cc) >> 1] = packbf(v2, v3);
        }
    }
}

// ---------------- K5: p=LN(Pb;s_n); x += xs + s_gamma*p; XAb = LN(x; n2) --------
__global__ void k_fuse1(const float* __restrict__ sng, const float* __restrict__ snb,
                        const float* __restrict__ sgam,
                        const float* __restrict__ n2g, const float* __restrict__ n2b) {
    int warp = threadIdx.x >> 5, lane = threadIdx.x & 31;
    int row = blockIdx.x * 8 + warp;
    int bidx = row*CC;
    uint2 pv0 = ((const uint2*)(g_Pb+bidx))[lane], pv1 = ((const uint2*)(g_Pb+bidx))[lane+32];
    float pf[8];
    unpack4(pv0, pf); unpack4(pv1, pf+4);
    float s = 0.f;
    #pragma unroll
    for (int j = 0; j < 8; j++) s += pf[j];
    float m1 = warpSum(s) * (1.f/CC);
    float vs = 0.f;
    #pragma unroll
    for (int j = 0; j < 8; j++) { pf[j] -= m1; vs += pf[j]*pf[j]; }
    float r1 = rsqrtf(warpSum(vs) * (1.f/CC) + EPSI);
    float4 ga = ((const float4*)sng)[lane], gb = ((const float4*)sng)[lane+32];
    float4 ba = ((const float4*)snb)[lane], bb = ((const float4*)snb)[lane+32];
    float gf[8] = {ga.x,ga.y,ga.z,ga.w,gb.x,gb.y,gb.z,gb.w};
    float bf_[8] = {ba.x,ba.y,ba.z,ba.w,bb.x,bb.y,bb.z,bb.w};
    float gamma = sgam[0];
    float4 x0 = ((const float4*)(g_X+bidx))[lane],  x1 = ((const float4*)(g_X+bidx))[lane+32];
    float4 s0 = ((const float4*)(g_XA+bidx))[lane], s1 = ((const float4*)(g_XA+bidx))[lane+32];
    float xf[8] = {x0.x,x0.y,x0.z,x0.w,x1.x,x1.y,x1.z,x1.w};
    float sf[8] = {s0.x,s0.y,s0.z,s0.w,s1.x,s1.y,s1.z,s1.w};
    float xn[8];
    #pragma unroll
    for (int j = 0; j < 8; j++)
        xn[j] = xf[j] + sf[j] + gamma * (pf[j]*r1*gf[j] + bf_[j]);
    float4 w0 = {xn[0],xn[1],xn[2],xn[3]}, w1 = {xn[4],xn[5],xn[6],xn[7]};
    ((float4*)(g_X+bidx))[lane] = w0; ((float4*)(g_X+bidx))[lane+32] = w1;
    float s2 = 0.f;
    #pragma unroll
    for (int j = 0; j < 8; j++) s2 += xn[j];
    float m2 = warpSum(s2) * (1.f/CC);
    float vs2 = 0.f;
    #pragma unroll
    for (int j = 0; j < 8; j++) { xn[j] -= m2; vs2 += xn[j]*xn[j]; }
    float r2 = rsqrtf(warpSum(vs2) * (1.f/CC) + EPSI);
    float4 g2a = ((const float4*)n2g)[lane], g2b = ((const float4*)n2g)[lane+32];
    float4 b2a = ((const float4*)n2b)[lane], b2b = ((const float4*)n2b)[lane+32];
    float g2f[8] = {g2a.x,g2a.y,g2a.z,g2a.w,g2b.x,g2b.y,g2b.z,g2b.w};
    float b2f[8] = {b2a.x,b2a.y,b2a.z,b2a.w,b2b.x,b2b.y,b2b.z,b2b.w};
    float o[8];
    #pragma unroll
    for (int j = 0; j < 8; j++) o[j] = xn[j]*r2*g2f[j] + b2f[j];
    uint2* Ob2 = (uint2*)(g_XAb + bidx);
    uint2 q0; q0.x = packbf(o[0],o[1]); q0.y = packbf(o[2],o[3]);
    uint2 q1; q1.x = packbf(o[4],o[5]); q1.y = packbf(o[6],o[7]);
    Ob2[lane] = q0; Ob2[lane+32] = q1;
}

// ---------------- K9: x += t_gamma*Pb; XAb = LN(x; n3) ----------------
__global__ void k_fuse2(const float* __restrict__ tgam,
                        const float* __restrict__ n3g, const float* __restrict__ n3b) {
    int warp = threadIdx.x >> 5, lane = threadIdx.x & 31;
    int row = blockIdx.x * 8 + warp;
    int bidx = row*CC;
    float gamma = tgam[0];
    uint2 pv0 = ((const uint2*)(g_Pb+bidx))[lane], pv1 = ((const uint2*)(g_Pb+bidx))[lane+32];
    float pf[8];
    unpack4(pv0, pf); unpack4(pv1, pf+4);
    float4 x0 = ((const float4*)(g_X+bidx))[lane], x1 = ((const float4*)(g_X+bidx))[lane+32];
    float xn[8] = {x0.x + gamma*pf[0], x0.y + gamma*pf[1], x0.z + gamma*pf[2], x0.w + gamma*pf[3],
                   x1.x + gamma*pf[4], x1.y + gamma*pf[5], x1.z + gamma*pf[6], x1.w + gamma*pf[7]};
    float4 w0 = {xn[0],xn[1],xn[2],xn[3]}, w1 = {xn[4],xn[5],xn[6],xn[7]};
    ((float4*)(g_X+bidx))[lane] = w0; ((float4*)(g_X+bidx))[lane+32] = w1;
    float s = 0.f;
    #pragma unroll
    for (int j = 0; j < 8; j++) s += xn[j];
    float m = warpSum(s) * (1.f/CC);
    float vs = 0.f;
    #pragma unroll
    for (int j = 0; j < 8; j++) { xn[j] -= m; vs += xn[j]*xn[j]; }
    float r = rsqrtf(warpSum(vs) * (1.f/CC) + EPSI);
    float4 ga = ((const float4*)n3g)[lane], gb = ((const float4*)n3g)[lane+32];
    float4 ba = ((const float4*)n3b)[lane], bb = ((const float4*)n3b)[lane+32];
    float gf[8] = {ga.x,ga.y,ga.z,ga.w,gb.x,gb.y,gb.z,gb.w};
    float bf_[8] = {ba.x,ba.y,ba.z,ba.w,bb.x,bb.y,bb.z,bb.w};
    float o[8];
    #pragma unroll
    for (int j = 0; j < 8; j++) o[j] = xn[j]*r*gf[j] + bf_[j];
    uint2* Ob2 = (uint2*)(g_XAb + bidx);
    uint2 q0; q0.x = packbf(o[0],o[1]); q0.y = packbf(o[2],o[3]);
    uint2 q1; q1.x = packbf(o[4],o[5]); q1.y = packbf(o[6],o[7]);
    Ob2[lane] = q0; Ob2[lane+32] = q1;
}

// ---------------- K12: temporal downsample ----------------
__global__ void k_down(float* __restrict__ out) {
    int i = blockIdx.x * blockDim.x + threadIdx.x;
    const float4* X4 = (const float4*)g_X;
    const int EC4 = EE*CC/4;
    int ec = i % EC4;
    int rest = i / EC4;
    int t2 = rest % 48;
    int b  = rest / 48;
    int in0 = (b*96 + 2*t2) * EC4 + ec;
    float4 a = X4[in0], c = X4[in0 + EC4];
    float4 o;
    o.x = 0.5f*(a.x + c.x); o.y = 0.5f*(a.y + c.y);
    o.z = 0.5f*(a.z + c.z); o.w = 0.5f*(a.w + c.w);
    ((float4*)out)[i] = o;
}

// ---------------- host ----------------
extern "C" void kernel_launch(void* const* d_in, const int* in_sizes, int n_in,
                              void* d_out, int out_size) {
    const float* x    = (const float*)d_in[0];
    const float* adj  = (const float*)d_in[1];
    const float* n1g  = (const float*)d_in[2];
    const float* n1b  = (const float*)d_in[3];
    const float* swq  = (const float*)d_in[4];
    const float* swk  = (const float*)d_in[5];
    const float* swv  = (const float*)d_in[6];
    const float* swp  = (const float*)d_in[7];
    const float* sbp  = (const float*)d_in[8];
    const float* sng  = (const float*)d_in[9];
    const float* snb  = (const float*)d_in[10];
    const float* sgam = (const float*)d_in[11];
    const float* n2g  = (const float*)d_in[12];
    const float* n2b  = (const float*)d_in[13];
    const float* twq  = (const float*)d_in[14];
    const float* twk  = (const float*)d_in[15];
    const float* twv  = (const float*)d_in[16];
    const float* twp  = (const float*)d_in[17];
    const float* tbp  = (const float*)d_in[18];
    const float* tgam = (const float*)d_in[19];
    const float* n3g  = (const float*)d_in[20];
    const float* n3b  = (const float*)d_in[21];
    const float* mw1  = (const float*)d_in[22];
    const float* mb1  = (const float*)d_in[23];
    const float* mw2  = (const float*)d_in[24];
    const float* mb2  = (const float*)d_in[25];

    float *X;
    __nv_bfloat16 *XAb, *QKVb, *Ob, *Pb, *Hb, *WB;
    cudaGetSymbolAddress((void**)&X,    g_X);
    cudaGetSymbolAddress((void**)&XAb,  g_XAb);
    cudaGetSymbolAddress((void**)&QKVb, g_QKVb);
    cudaGetSymbolAddress((void**)&Ob,   g_Ob);
    cudaGetSymbolAddress((void**)&Pb,   g_Pb);
    cudaGetSymbolAddress((void**)&Hb,   g_Hb);
    cudaGetSymbolAddress((void**)&WB,   g_WB);

    cudaFuncSetAttribute(attn_mma<false>, cudaFuncAttributeMaxDynamicSharedMemorySize, ATTN_SMEM);
    cudaFuncSetAttribute(attn_mma<true>,  cudaFuncAttributeMaxDynamicSharedMemorySize, ATTN_SMEM);

    dim3 g256(2, NROWS/128);     // N=256
    dim3 g768(6, NROWS/128);     // N=768 fused QKV
    dim3 g1024(8, NROWS/128);    // N=1024

    k_wconv<<<2048, 256>>>(swq, swk, swv, swp, twq, twk, twv, twp, mw1, mw2);

    // ---- spatial block ----
    k_ln1<<<NROWS/8, 256>>>(x, n1g, n1b);
    hgemm_k<0,1><<<g768, 256>>>(XAb, WB+W_SQ, nullptr, nullptr, QKVb, NROWS, 768, CC);
    attn_mma<false><<<dim3(BB*TT, HH), 256, ATTN_SMEM>>>(QKVb, Ob, adj);
    hgemm_k<1,1><<<g256, 256>>>(Ob, WB+W_SP, sbp, nullptr, Pb, NROWS, CC, CC);
    k_fuse1<<<NROWS/8, 256>>>(sng, snb, sgam, n2g, n2b);

    // ---- temporal block ----
    hgemm_k<0,1><<<g768, 256>>>(XAb, WB+W_TQ, nullptr, nullptr, QKVb, NROWS, 768, CC);
    attn_mma<true><<<dim3(BB*EE, HH), 256, ATTN_SMEM>>>(QKVb, Ob, nullptr);
    hgemm_k<1,1><<<g256, 256>>>(Ob, WB+W_TP, tbp, nullptr, Pb, NROWS, CC, CC);
    k_fuse2<<<NROWS/8, 256>>>(tgam, n3g, n3b);

    // ---- MLP ----
    hgemm_k<2,1><<<g1024, 256>>>(XAb, WB+W_M1, mb1, nullptr, Hb, NROWS, HIDN, CC);
    hgemm_k<3,0><<<g256, 256>>>(Hb, WB+W_M2, mb2, X, X, NROWS, CC, HIDN);

    // ---- downsample ----
    k_down<<<(BB*48*EE*CC/4)/256, 256>>>((float*)d_out);

    (void)in_sizes; (void)n_in; (void)out_size;
}